// round 3
// baseline (speedup 1.0000x reference)
#include <cuda_runtime.h>
#include <cstdint>

// Problem constants (fixed by the dataset): N=100000, E=1600000, F=128, H=4, C=32
#define NMAX 100000
#define EMAX 1600000

// Scratch (device globals — allocation-free per harness rules)
__device__ __align__(16) float g_h[(size_t)NMAX * 128];    // 51.2 MB
__device__ __align__(16) float g_asrc[(size_t)NMAX * 4];
__device__ __align__(16) float g_adst[(size_t)NMAX * 4];
__device__ __align__(16) float g_ssum[(size_t)NMAX * 4];
__device__ int g_is64;

__device__ __forceinline__ void red_add_v4(float* addr, float4 v) {
    asm volatile("red.global.add.v4.f32 [%0], {%1,%2,%3,%4};"
                 :: "l"(addr), "f"(v.x), "f"(v.y), "f"(v.z), "f"(v.w)
                 : "memory");
}

// Fetch (src,dst) for item e; items [0,E) are edges, [E,E+N) self-loops.
__device__ __forceinline__ void edge_sd(const void* ei, int e, int E, int N,
                                        int& s, int& d) {
    if (e >= E) { s = d = e - E; return; }
    if (g_is64) {
        const long long* p = (const long long*)ei;
        s = (int)__ldg(p + e); d = (int)__ldg(p + (size_t)E + e);
    } else {
        const int* p = (const int*)ei;
        s = __ldg(p + e); d = __ldg(p + (size_t)E + e);
    }
}

// ---------------------------------------------------------------------------
// K_detect: probe edge_index dtype. Reads first 8 candidates as int64 (64 B,
// always within the buffer). Genuine int64 indices lie in [0,N); int32 data
// read as int64 packs two indices -> value >= 2^32 almost surely.
// ---------------------------------------------------------------------------
__global__ void k_detect(const void* ei, int N) {
    const long long* p = (const long long*)ei;
    bool ok64 = true;
#pragma unroll
    for (int i = 0; i < 8; i++) {
        long long v = p[i];
        if (v < 0 || v >= N) ok64 = false;
    }
    g_is64 = ok64 ? 1 : 0;
}

// ---------------------------------------------------------------------------
// K0: out rows <- bias (out is poisoned by harness), s_sum <- 0
// ---------------------------------------------------------------------------
__global__ void k_init(float* __restrict__ out, const float* __restrict__ bias, int N) {
    int i = blockIdx.x * blockDim.x + threadIdx.x;   // N*32 float4 slots
    if (i < N * 32) {
        int c = i & 31;
        ((float4*)out)[i] = ((const float4*)bias)[c];
    }
    if (i < N) {
        ((float4*)g_ssum)[i] = make_float4(0.f, 0.f, 0.f, 0.f);
    }
}

// ---------------------------------------------------------------------------
// K1: h = x @ W   (N x 128) = (N x 128)(128 x 128), fp32
// 64 rows per block, K tiled by 32. Each thread: 4 cols x 8 rows.
// ---------------------------------------------------------------------------
__global__ void __launch_bounds__(256) k_gemm(const float* __restrict__ x,
                                              const float* __restrict__ W, int N) {
    __shared__ float Ws[32 * 128];   // [k][col]  16 KB
    __shared__ float Xs[64 * 32];    // [row][k]   8 KB

    const int tid = threadIdx.x;
    const int tx = tid & 31;         // col group: cols 4*tx..4*tx+3
    const int ty = tid >> 5;         // 0..7 -> rows ty*8..ty*8+7
    const int row0 = blockIdx.x * 64;
    const int rbase = ty * 8;

    float4 acc[8];
#pragma unroll
    for (int r = 0; r < 8; r++) acc[r] = make_float4(0.f, 0.f, 0.f, 0.f);

    const float4* Xg = (const float4*)x;
    const float4* Wg = (const float4*)W;
    float4* Ws4 = (float4*)Ws;
    float4* Xs4 = (float4*)Xs;

    for (int kt = 0; kt < 4; kt++) {
#pragma unroll
        for (int i = 0; i < 4; i++) {
            int idx = tid + i * 256;               // 0..1023
            int r = idx >> 5, c = idx & 31;
            Ws4[idx] = Wg[(size_t)(kt * 32 + r) * 32 + c];
        }
#pragma unroll
        for (int i = 0; i < 2; i++) {
            int idx = tid + i * 256;               // 0..511
            int r = idx >> 3, c = idx & 7;
            int gr = row0 + r;
            Xs4[idx] = (gr < N) ? Xg[(size_t)gr * 32 + kt * 8 + c]
                                : make_float4(0.f, 0.f, 0.f, 0.f);
        }
        __syncthreads();

#pragma unroll 8
        for (int kk = 0; kk < 32; kk++) {
            float4 w = Ws4[kk * 32 + tx];
#pragma unroll
            for (int r = 0; r < 8; r++) {
                float xv = Xs[(rbase + r) * 32 + kk];
                acc[r].x = fmaf(w.x, xv, acc[r].x);
                acc[r].y = fmaf(w.y, xv, acc[r].y);
                acc[r].z = fmaf(w.z, xv, acc[r].z);
                acc[r].w = fmaf(w.w, xv, acc[r].w);
            }
        }
        __syncthreads();
    }

#pragma unroll
    for (int r = 0; r < 8; r++) {
        int gr = row0 + rbase + r;
        if (gr < N) ((float4*)(g_h + (size_t)gr * 128))[tx] = acc[r];
    }
}

// ---------------------------------------------------------------------------
// K2: per-node attention logits  a_src[n,h] = <h[n,h,:], att_src[h,:]>
// one warp per node; lane holds float4 at offset lane*4 (head = lane/8)
// ---------------------------------------------------------------------------
__global__ void k_attn(const float* __restrict__ att_src,
                       const float* __restrict__ att_dst, int N) {
    int gw = (blockIdx.x * blockDim.x + threadIdx.x) >> 5;
    int lane = threadIdx.x & 31;
    if (gw >= N) return;

    float4 hv = ((const float4*)(g_h + (size_t)gw * 128))[lane];
    float4 s4 = ((const float4*)att_src)[lane];
    float4 d4 = ((const float4*)att_dst)[lane];

    float ps = hv.x * s4.x + hv.y * s4.y + hv.z * s4.z + hv.w * s4.w;
    float pd = hv.x * d4.x + hv.y * d4.y + hv.z * d4.z + hv.w * d4.w;

#pragma unroll
    for (int off = 4; off; off >>= 1) {
        ps += __shfl_xor_sync(0xFFFFFFFFu, ps, off);
        pd += __shfl_xor_sync(0xFFFFFFFFu, pd, off);
    }
    if ((lane & 7) == 0) {
        int hh = lane >> 3;
        g_asrc[gw * 4 + hh] = ps;
        g_adst[gw * 4 + hh] = pd;
    }
}

// ---------------------------------------------------------------------------
// K3: edge pass 1 — accumulate softmax denominators (no max shift needed:
// |e| <= ~5 with these input scales, exp() safe in fp32; EPS=1e-16 negligible)
// ---------------------------------------------------------------------------
__global__ void k_edge_sum(const void* __restrict__ ei, int E, int N) {
    int e = blockIdx.x * blockDim.x + threadIdx.x;
    if (e >= E + N) return;
    int s, d;
    edge_sd(ei, e, E, N, s, d);

    float4 as = *(const float4*)(g_asrc + (size_t)s * 4);
    float4 ad = *(const float4*)(g_adst + (size_t)d * 4);
    float4 p;
    float v;
    v = as.x + ad.x; v = v > 0.f ? v : 0.2f * v; p.x = __expf(v);
    v = as.y + ad.y; v = v > 0.f ? v : 0.2f * v; p.y = __expf(v);
    v = as.z + ad.z; v = v > 0.f ? v : 0.2f * v; p.z = __expf(v);
    v = as.w + ad.w; v = v > 0.f ? v : 0.2f * v; p.w = __expf(v);

    red_add_v4(g_ssum + (size_t)d * 4, p);
}

// ---------------------------------------------------------------------------
// K4: edge pass 2 — scatter messages. One warp per edge; lane owns float4
// of the 128-wide feature row. alpha recomputed (a-arrays are L1/L2 hot).
// ---------------------------------------------------------------------------
__global__ void k_edge_scatter(const void* __restrict__ ei,
                               float* __restrict__ out, int E, int N) {
    int gw = (blockIdx.x * blockDim.x + threadIdx.x) >> 5;
    int lane = threadIdx.x & 31;
    if (gw >= E + N) return;
    int s, d;
    edge_sd(ei, gw, E, N, s, d);

    int hh = lane >> 3;
    float a = g_asrc[(size_t)s * 4 + hh] + g_adst[(size_t)d * 4 + hh];
    a = a > 0.f ? a : 0.2f * a;
    float alpha = __fdividef(__expf(a), g_ssum[(size_t)d * 4 + hh]);

    float4 hv = ((const float4*)(g_h + (size_t)s * 128))[lane];
    float4 m = make_float4(hv.x * alpha, hv.y * alpha, hv.z * alpha, hv.w * alpha);
    red_add_v4(out + (size_t)d * 128 + lane * 4, m);
}

// ---------------------------------------------------------------------------
extern "C" void kernel_launch(void* const* d_in, const int* in_sizes, int n_in,
                              void* d_out, int out_size) {
    // Classify inputs by element count — robust to metadata ordering.
    int idx_W = -1;
    int small[3] = {-1, -1, -1}; int ns = 0;
    for (int i = 0; i < n_in; i++) {
        int sz = in_sizes[i];
        if (sz == 128 && ns < 3)  small[ns++] = i;
        else if (sz == 128 * 128) idx_W = i;
    }
    int idx_x = -1, idx_e = -1;
    for (int i = 0; i < n_in; i++) {
        if (in_sizes[i] == 128 || in_sizes[i] == 128 * 128) continue;
        if (idx_x < 0 || in_sizes[i] > in_sizes[idx_x]) { idx_e = idx_x; idx_x = i; }
        else if (idx_e < 0 || in_sizes[i] > in_sizes[idx_e]) { idx_e = i; }
    }
    int idx_asrc, idx_adst, idx_bias;
    if (idx_x < small[0]) {          // signature/dict order: att_src, att_dst, bias
        idx_asrc = small[0]; idx_adst = small[1]; idx_bias = small[2];
    } else {                         // alphabetical: att_dst, att_src, bias
        idx_adst = small[0]; idx_asrc = small[1]; idx_bias = small[2];
    }

    const float* x       = (const float*)d_in[idx_x];
    const void*  ei      = d_in[idx_e];
    const float* W       = (const float*)d_in[idx_W];
    const float* att_src = (const float*)d_in[idx_asrc];
    const float* att_dst = (const float*)d_in[idx_adst];
    const float* bias    = (const float*)d_in[idx_bias];
    float* out           = (float*)d_out;

    const int N = in_sizes[idx_x] / 128;
    const int E = in_sizes[idx_e] / 2;

    k_detect<<<1, 1>>>(ei, N);

    {   // K0: init out=bias rows, ssum=0
        int tot = N * 32;
        k_init<<<(tot + 255) / 256, 256>>>(out, bias, N);
    }
    k_gemm<<<(N + 63) / 64, 256>>>(x, W, N);
    k_attn<<<(N * 32 + 255) / 256, 256>>>(att_src, att_dst, N);
    {
        int total = E + N;
        k_edge_sum<<<(total + 255) / 256, 256>>>(ei, E, N);
    }
    {
        long long total = (long long)E + N;
        long long threads = total * 32;
        int blocks = (int)((threads + 255) / 256);
        k_edge_scatter<<<blocks, 256>>>(ei, out, E, N);
    }
}

// round 4
// speedup vs baseline: 1.3030x; 1.3030x over previous
#include <cuda_runtime.h>
#include <cstdint>

// Problem constants (dataset-fixed): N=100000, E=1600000, F=128, H=4, C=32
#define NMAX 100000
#define EMAX 1600000

// Scratch (device globals — allocation-free per harness rules)
__device__ __align__(16) float g_h[(size_t)NMAX * 128];    // 51.2 MB
__device__ __align__(16) float g_asrc[(size_t)NMAX * 4];
__device__ __align__(16) float g_adst[(size_t)NMAX * 4];
__device__ int g_deg[NMAX + 1];
__device__ int g_off[NMAX + 1];
__device__ int g_cur[NMAX];
__device__ int g_csrc[EMAX];                               // CSR src ids, 6.4 MB
__device__ int g_is64;

__device__ __forceinline__ float sel4(float4 v, int h) {
    float a = (h & 1) ? v.y : v.x;
    float b = (h & 1) ? v.w : v.z;
    return (h & 2) ? b : a;
}
__device__ __forceinline__ float lrelu(float v) { return v > 0.f ? v : 0.2f * v; }

// ---------------------------------------------------------------------------
// dtype probe: first 8 values read as int64 all in [0,N) => really int64.
// ---------------------------------------------------------------------------
__global__ void k_detect(const void* ei, int N) {
    const long long* p = (const long long*)ei;
    bool ok64 = true;
#pragma unroll
    for (int i = 0; i < 8; i++) {
        long long v = p[i];
        if (v < 0 || v >= N) ok64 = false;
    }
    g_is64 = ok64 ? 1 : 0;
}

__device__ __forceinline__ int edge_src(const void* ei, int e) {
    return g_is64 ? (int)__ldg((const long long*)ei + e)
                  : __ldg((const int*)ei + e);
}
__device__ __forceinline__ int edge_dst(const void* ei, int e, int E) {
    return g_is64 ? (int)__ldg((const long long*)ei + (size_t)E + e)
                  : __ldg((const int*)ei + (size_t)E + e);
}

// ---------------------------------------------------------------------------
// CSR build: zero, histogram, scan, scatter
// ---------------------------------------------------------------------------
__global__ void k_zero(int N) {
    int i = blockIdx.x * blockDim.x + threadIdx.x;
    if (i <= N) g_deg[i] = 0;
}

__global__ void k_hist(const void* __restrict__ ei, int E) {
    int e = blockIdx.x * blockDim.x + threadIdx.x;
    if (e < E) atomicAdd(&g_deg[edge_dst(ei, e, E)], 1);
}

// single-block exclusive scan of g_deg[0..n) -> g_off, g_cur
__global__ void __launch_bounds__(1024) k_scan(int n) {
    __shared__ int warp_sums[32];
    __shared__ int s_carry;
    const int tid = threadIdx.x, lane = tid & 31, wid = tid >> 5;
    if (tid == 0) s_carry = 0;
    __syncthreads();
    for (int base = 0; base < n; base += 1024) {
        int i = base + tid;
        int v = (i < n) ? g_deg[i] : 0;
        int x = v;
#pragma unroll
        for (int off = 1; off < 32; off <<= 1) {
            int y = __shfl_up_sync(0xFFFFFFFFu, x, off);
            if (lane >= off) x += y;
        }
        if (lane == 31) warp_sums[wid] = x;
        __syncthreads();
        if (wid == 0) {
            int s = warp_sums[lane];
#pragma unroll
            for (int off = 1; off < 32; off <<= 1) {
                int y = __shfl_up_sync(0xFFFFFFFFu, s, off);
                if (lane >= off) s += y;
            }
            warp_sums[lane] = s;
        }
        __syncthreads();
        int incl = x + (wid ? warp_sums[wid - 1] : 0);
        int carry = s_carry;
        if (i < n) {
            int excl = carry + incl - v;
            g_off[i] = excl;
            g_cur[i] = excl;
        }
        __syncthreads();
        if (tid == 1023) s_carry = carry + incl;
        __syncthreads();
    }
    if (threadIdx.x == 0) g_off[n] = s_carry;
}

__global__ void k_csr(const void* __restrict__ ei, int E) {
    int e = blockIdx.x * blockDim.x + threadIdx.x;
    if (e >= E) return;
    int s = edge_src(ei, e);
    int d = edge_dst(ei, e, E);
    int pos = atomicAdd(&g_cur[d], 1);
    g_csrc[pos] = s;
}

// ---------------------------------------------------------------------------
// GEMM h = x @ W with fused attention-logit epilogue.
// 64 rows/block, 256 thr; warp = 8 rows x all 128 cols (tx covers cols 4tx..).
// ---------------------------------------------------------------------------
__global__ void __launch_bounds__(256) k_gemm(const float* __restrict__ x,
                                              const float* __restrict__ W,
                                              const float* __restrict__ att_src,
                                              const float* __restrict__ att_dst,
                                              int N) {
    __shared__ float Ws[32 * 128];
    __shared__ float Xs[64 * 32];

    const int tid = threadIdx.x;
    const int tx = tid & 31;
    const int ty = tid >> 5;
    const int row0 = blockIdx.x * 64;
    const int rbase = ty * 8;

    float4 acc[8];
#pragma unroll
    for (int r = 0; r < 8; r++) acc[r] = make_float4(0.f, 0.f, 0.f, 0.f);

    const float4* Xg = (const float4*)x;
    const float4* Wg = (const float4*)W;
    float4* Ws4 = (float4*)Ws;
    float4* Xs4 = (float4*)Xs;

    for (int kt = 0; kt < 4; kt++) {
#pragma unroll
        for (int i = 0; i < 4; i++) {
            int idx = tid + i * 256;
            int r = idx >> 5, c = idx & 31;
            Ws4[idx] = Wg[(size_t)(kt * 32 + r) * 32 + c];
        }
#pragma unroll
        for (int i = 0; i < 2; i++) {
            int idx = tid + i * 256;
            int r = idx >> 3, c = idx & 7;
            int gr = row0 + r;
            Xs4[idx] = (gr < N) ? Xg[(size_t)gr * 32 + kt * 8 + c]
                                : make_float4(0.f, 0.f, 0.f, 0.f);
        }
        __syncthreads();

#pragma unroll 8
        for (int kk = 0; kk < 32; kk++) {
            float4 w = Ws4[kk * 32 + tx];
#pragma unroll
            for (int r = 0; r < 8; r++) {
                float xv = Xs[(rbase + r) * 32 + kk];
                acc[r].x = fmaf(w.x, xv, acc[r].x);
                acc[r].y = fmaf(w.y, xv, acc[r].y);
                acc[r].z = fmaf(w.z, xv, acc[r].z);
                acc[r].w = fmaf(w.w, xv, acc[r].w);
            }
        }
        __syncthreads();
    }

    float4 s4 = ((const float4*)att_src)[tx];
    float4 d4 = ((const float4*)att_dst)[tx];

#pragma unroll
    for (int r = 0; r < 8; r++) {
        int gr = row0 + rbase + r;
        if (gr < N) ((float4*)(g_h + (size_t)gr * 128))[tx] = acc[r];
        float ps = acc[r].x * s4.x + acc[r].y * s4.y + acc[r].z * s4.z + acc[r].w * s4.w;
        float pd = acc[r].x * d4.x + acc[r].y * d4.y + acc[r].z * d4.z + acc[r].w * d4.w;
#pragma unroll
        for (int off = 4; off; off >>= 1) {
            ps += __shfl_xor_sync(0xFFFFFFFFu, ps, off);
            pd += __shfl_xor_sync(0xFFFFFFFFu, pd, off);
        }
        if ((tx & 7) == 0 && gr < N) {
            int hh = tx >> 3;
            g_asrc[(size_t)gr * 4 + hh] = ps;
            g_adst[(size_t)gr * 4 + hh] = pd;
        }
    }
}

// ---------------------------------------------------------------------------
// Aggregation: one warp per dst node. Pass1: softmax denominator over
// in-edges (+ self loop). Pass2: gather h[src]*alpha into registers.
// Single plain 512B store per node (+bias). Zero atomics.
// ---------------------------------------------------------------------------
__global__ void __launch_bounds__(256) k_agg(float* __restrict__ out,
                                             const float* __restrict__ bias,
                                             int N) {
    int d = (blockIdx.x * blockDim.x + threadIdx.x) >> 5;
    int lane = threadIdx.x & 31;
    if (d >= N) return;
    const int hh = lane >> 3;

    const float4 ad4 = *(const float4*)(g_adst + (size_t)d * 4);
    const int beg = g_off[d];
    const int end = g_off[d + 1];

    // ---- pass 1: denominators (all 4 heads), lane-strided over edges
    float4 den = make_float4(0.f, 0.f, 0.f, 0.f);
    for (int j = beg + lane; j < end; j += 32) {
        int s = __ldg(&g_csrc[j]);
        float4 as = *(const float4*)(g_asrc + (size_t)s * 4);
        den.x += __expf(lrelu(as.x + ad4.x));
        den.y += __expf(lrelu(as.y + ad4.y));
        den.z += __expf(lrelu(as.z + ad4.z));
        den.w += __expf(lrelu(as.w + ad4.w));
    }
    if (lane == 0) {  // self loop
        float4 as = *(const float4*)(g_asrc + (size_t)d * 4);
        den.x += __expf(lrelu(as.x + ad4.x));
        den.y += __expf(lrelu(as.y + ad4.y));
        den.z += __expf(lrelu(as.z + ad4.z));
        den.w += __expf(lrelu(as.w + ad4.w));
    }
#pragma unroll
    for (int off = 16; off; off >>= 1) {
        den.x += __shfl_xor_sync(0xFFFFFFFFu, den.x, off);
        den.y += __shfl_xor_sync(0xFFFFFFFFu, den.y, off);
        den.z += __shfl_xor_sync(0xFFFFFFFFu, den.z, off);
        den.w += __shfl_xor_sync(0xFFFFFFFFu, den.w, off);
    }
    const float inv = 1.0f / sel4(den, hh);
    const float adst_h = sel4(ad4, hh);

    // ---- pass 2: weighted gather, register accumulate
    float4 acc = make_float4(0.f, 0.f, 0.f, 0.f);
    for (int j = beg; j < end; j++) {
        int s = __ldg(&g_csrc[j]);
        float alpha = __expf(lrelu(__ldg(&g_asrc[(size_t)s * 4 + hh]) + adst_h)) * inv;
        float4 hv = ((const float4*)(g_h + (size_t)s * 128))[lane];
        acc.x = fmaf(hv.x, alpha, acc.x);
        acc.y = fmaf(hv.y, alpha, acc.y);
        acc.z = fmaf(hv.z, alpha, acc.z);
        acc.w = fmaf(hv.w, alpha, acc.w);
    }
    {   // self loop
        float alpha = __expf(lrelu(__ldg(&g_asrc[(size_t)d * 4 + hh]) + adst_h)) * inv;
        float4 hv = ((const float4*)(g_h + (size_t)d * 128))[lane];
        acc.x = fmaf(hv.x, alpha, acc.x);
        acc.y = fmaf(hv.y, alpha, acc.y);
        acc.z = fmaf(hv.z, alpha, acc.z);
        acc.w = fmaf(hv.w, alpha, acc.w);
    }

    float4 b4 = ((const float4*)bias)[lane];
    acc.x += b4.x; acc.y += b4.y; acc.z += b4.z; acc.w += b4.w;
    ((float4*)(out + (size_t)d * 128))[lane] = acc;
}

// ---------------------------------------------------------------------------
extern "C" void kernel_launch(void* const* d_in, const int* in_sizes, int n_in,
                              void* d_out, int out_size) {
    // Classify inputs by element count — robust to metadata ordering.
    int idx_W = -1;
    int small[3] = {-1, -1, -1}; int ns = 0;
    for (int i = 0; i < n_in; i++) {
        int sz = in_sizes[i];
        if (sz == 128 && ns < 3)  small[ns++] = i;
        else if (sz == 128 * 128) idx_W = i;
    }
    int idx_x = -1, idx_e = -1;
    for (int i = 0; i < n_in; i++) {
        if (in_sizes[i] == 128 || in_sizes[i] == 128 * 128) continue;
        if (idx_x < 0 || in_sizes[i] > in_sizes[idx_x]) { idx_e = idx_x; idx_x = i; }
        else if (idx_e < 0 || in_sizes[i] > in_sizes[idx_e]) { idx_e = i; }
    }
    int idx_asrc, idx_adst, idx_bias;
    if (idx_x < small[0]) {          // signature/dict order: att_src, att_dst, bias
        idx_asrc = small[0]; idx_adst = small[1]; idx_bias = small[2];
    } else {                         // alphabetical: att_dst, att_src, bias
        idx_adst = small[0]; idx_asrc = small[1]; idx_bias = small[2];
    }

    const float* x       = (const float*)d_in[idx_x];
    const void*  ei      = d_in[idx_e];
    const float* W       = (const float*)d_in[idx_W];
    const float* att_src = (const float*)d_in[idx_asrc];
    const float* att_dst = (const float*)d_in[idx_adst];
    const float* bias    = (const float*)d_in[idx_bias];
    float* out           = (float*)d_out;

    const int N = in_sizes[idx_x] / 128;
    const int E = in_sizes[idx_e] / 2;

    k_detect<<<1, 1>>>(ei, N);

    // CSR build
    k_zero<<<(N + 256) / 256, 256>>>(N);
    k_hist<<<(E + 255) / 256, 256>>>(ei, E);
    k_scan<<<1, 1024>>>(N);
    k_csr<<<(E + 255) / 256, 256>>>(ei, E);

    // GEMM + fused attention logits
    k_gemm<<<(N + 63) / 64, 256>>>(x, W, att_src, att_dst, N);

    // Per-dst softmax + aggregation (warp per node)
    {
        long long threads = (long long)N * 32;
        int blocks = (int)((threads + 255) / 256);
        k_agg<<<blocks, 256>>>(out, bias, N);
    }
}

// round 5
// speedup vs baseline: 1.7013x; 1.3056x over previous
#include <cuda_runtime.h>
#include <cstdint>

// Problem constants (dataset-fixed): N=100000, E=1600000, F=128, H=4, C=32
#define NMAX 100000
#define EMAX 1600000

// Scratch (device globals — allocation-free per harness rules)
__device__ __align__(16) float g_h[(size_t)NMAX * 128];    // 51.2 MB
__device__ __align__(16) float g_asrc[(size_t)NMAX * 4];
__device__ __align__(16) float g_adst[(size_t)NMAX * 4];
__device__ int g_deg[NMAX + 1];
__device__ int g_off[NMAX + 1];
__device__ int g_cur[NMAX];
__device__ int g_csrc[EMAX];                               // CSR src ids, 6.4 MB
__device__ int g_bsum[256];                                // per-block scan totals
__device__ int g_bpre[256];                                // exclusive prefix of totals
__device__ int g_is64;

__device__ __forceinline__ float sel4(float4 v, int h) {
    float a = (h & 1) ? v.y : v.x;
    float b = (h & 1) ? v.w : v.z;
    return (h & 2) ? b : a;
}
__device__ __forceinline__ float lrelu(float v) { return v > 0.f ? v : 0.2f * v; }

// ---------------------------------------------------------------------------
// dtype probe: first 8 values read as int64 all in [0,N) => really int64.
// ---------------------------------------------------------------------------
__global__ void k_detect(const void* ei, int N) {
    const long long* p = (const long long*)ei;
    bool ok64 = true;
#pragma unroll
    for (int i = 0; i < 8; i++) {
        long long v = p[i];
        if (v < 0 || v >= N) ok64 = false;
    }
    g_is64 = ok64 ? 1 : 0;
}

__device__ __forceinline__ int edge_src(const void* ei, int e) {
    return g_is64 ? (int)__ldg((const long long*)ei + e)
                  : __ldg((const int*)ei + e);
}
__device__ __forceinline__ int edge_dst(const void* ei, int e, int E) {
    return g_is64 ? (int)__ldg((const long long*)ei + (size_t)E + e)
                  : __ldg((const int*)ei + (size_t)E + e);
}

// ---------------------------------------------------------------------------
// CSR build: zero, histogram, hierarchical scan (3 phases), scatter
// ---------------------------------------------------------------------------
__global__ void k_zero(int N) {
    int i = blockIdx.x * blockDim.x + threadIdx.x;
    if (i <= N) g_deg[i] = 0;
}

__global__ void k_hist(const void* __restrict__ ei, int E) {
    int e = blockIdx.x * blockDim.x + threadIdx.x;
    if (e < E) atomicAdd(&g_deg[edge_dst(ei, e, E)], 1);
}

// phase 1: per-block scan of 1024-element chunks
__global__ void __launch_bounds__(1024) k_scan1(int n) {
    __shared__ int warp_sums[32];
    const int tid = threadIdx.x, lane = tid & 31, wid = tid >> 5;
    int i = blockIdx.x * 1024 + tid;
    int v = (i < n) ? g_deg[i] : 0;
    int x = v;
#pragma unroll
    for (int off = 1; off < 32; off <<= 1) {
        int y = __shfl_up_sync(0xFFFFFFFFu, x, off);
        if (lane >= off) x += y;
    }
    if (lane == 31) warp_sums[wid] = x;
    __syncthreads();
    if (wid == 0) {
        int s = warp_sums[lane];
#pragma unroll
        for (int off = 1; off < 32; off <<= 1) {
            int y = __shfl_up_sync(0xFFFFFFFFu, s, off);
            if (lane >= off) s += y;
        }
        warp_sums[lane] = s;
    }
    __syncthreads();
    int incl = x + (wid ? warp_sums[wid - 1] : 0);
    if (i < n) g_off[i] = incl - v;          // block-local exclusive
    if (tid == 1023) g_bsum[blockIdx.x] = incl;
}

// phase 2: scan block totals (nb <= 256) — Hillis-Steele in smem
__global__ void __launch_bounds__(256) k_scan2(int nb) {
    __shared__ int s[256];
    int tid = threadIdx.x;
    s[tid] = (tid < nb) ? g_bsum[tid] : 0;
    __syncthreads();
#pragma unroll
    for (int off = 1; off < 256; off <<= 1) {
        int v = (tid >= off) ? s[tid - off] : 0;
        __syncthreads();
        s[tid] += v;
        __syncthreads();
    }
    if (tid < nb) g_bpre[tid] = s[tid] - g_bsum[tid];   // exclusive
}

// phase 3: add block prefix, fill g_cur, set sentinel
__global__ void __launch_bounds__(1024) k_scan3(int n, int E) {
    int i = blockIdx.x * 1024 + threadIdx.x;
    if (i < n) {
        int v = g_off[i] + g_bpre[blockIdx.x];
        g_off[i] = v;
        g_cur[i] = v;
    }
    if (i == n) g_off[n] = E;
}

__global__ void k_csr(const void* __restrict__ ei, int E) {
    int e = blockIdx.x * blockDim.x + threadIdx.x;
    if (e >= E) return;
    int s = edge_src(ei, e);
    int d = edge_dst(ei, e, E);
    int pos = atomicAdd(&g_cur[d], 1);
    g_csrc[pos] = s;
}

// ---------------------------------------------------------------------------
// GEMM h = x @ W with fused attention-logit epilogue.
// ---------------------------------------------------------------------------
__global__ void __launch_bounds__(256) k_gemm(const float* __restrict__ x,
                                              const float* __restrict__ W,
                                              const float* __restrict__ att_src,
                                              const float* __restrict__ att_dst,
                                              int N) {
    __shared__ float Ws[32 * 128];
    __shared__ float Xs[64 * 32];

    const int tid = threadIdx.x;
    const int tx = tid & 31;
    const int ty = tid >> 5;
    const int row0 = blockIdx.x * 64;
    const int rbase = ty * 8;

    float4 acc[8];
#pragma unroll
    for (int r = 0; r < 8; r++) acc[r] = make_float4(0.f, 0.f, 0.f, 0.f);

    const float4* Xg = (const float4*)x;
    const float4* Wg = (const float4*)W;
    float4* Ws4 = (float4*)Ws;
    float4* Xs4 = (float4*)Xs;

    for (int kt = 0; kt < 4; kt++) {
#pragma unroll
        for (int i = 0; i < 4; i++) {
            int idx = tid + i * 256;
            int r = idx >> 5, c = idx & 31;
            Ws4[idx] = Wg[(size_t)(kt * 32 + r) * 32 + c];
        }
#pragma unroll
        for (int i = 0; i < 2; i++) {
            int idx = tid + i * 256;
            int r = idx >> 3, c = idx & 7;
            int gr = row0 + r;
            Xs4[idx] = (gr < N) ? Xg[(size_t)gr * 32 + kt * 8 + c]
                                : make_float4(0.f, 0.f, 0.f, 0.f);
        }
        __syncthreads();

#pragma unroll 8
        for (int kk = 0; kk < 32; kk++) {
            float4 w = Ws4[kk * 32 + tx];
#pragma unroll
            for (int r = 0; r < 8; r++) {
                float xv = Xs[(rbase + r) * 32 + kk];
                acc[r].x = fmaf(w.x, xv, acc[r].x);
                acc[r].y = fmaf(w.y, xv, acc[r].y);
                acc[r].z = fmaf(w.z, xv, acc[r].z);
                acc[r].w = fmaf(w.w, xv, acc[r].w);
            }
        }
        __syncthreads();
    }

    float4 s4 = ((const float4*)att_src)[tx];
    float4 d4 = ((const float4*)att_dst)[tx];

#pragma unroll
    for (int r = 0; r < 8; r++) {
        int gr = row0 + rbase + r;
        if (gr < N) ((float4*)(g_h + (size_t)gr * 128))[tx] = acc[r];
        float ps = acc[r].x * s4.x + acc[r].y * s4.y + acc[r].z * s4.z + acc[r].w * s4.w;
        float pd = acc[r].x * d4.x + acc[r].y * d4.y + acc[r].z * d4.z + acc[r].w * d4.w;
#pragma unroll
        for (int off = 4; off; off >>= 1) {
            ps += __shfl_xor_sync(0xFFFFFFFFu, ps, off);
            pd += __shfl_xor_sync(0xFFFFFFFFu, pd, off);
        }
        if ((tx & 7) == 0 && gr < N) {
            int hh = tx >> 3;
            g_asrc[(size_t)gr * 4 + hh] = ps;
            g_adst[(size_t)gr * 4 + hh] = pd;
        }
    }
}

// ---------------------------------------------------------------------------
// Aggregation: one warp per dst node. Pass1: softmax denominator.
// Pass2: weighted gather into registers. One plain 512B store. Zero atomics.
// ---------------------------------------------------------------------------
__global__ void __launch_bounds__(256) k_agg(float* __restrict__ out,
                                             const float* __restrict__ bias,
                                             int N) {
    int d = (blockIdx.x * blockDim.x + threadIdx.x) >> 5;
    int lane = threadIdx.x & 31;
    if (d >= N) return;
    const int hh = lane >> 3;

    const float4 ad4 = *(const float4*)(g_adst + (size_t)d * 4);
    const int beg = g_off[d];
    const int end = g_off[d + 1];

    // ---- pass 1: denominators (all 4 heads), lane-strided over edges
    float4 den = make_float4(0.f, 0.f, 0.f, 0.f);
    for (int j = beg + lane; j < end; j += 32) {
        int s = __ldg(&g_csrc[j]);
        float4 as = *(const float4*)(g_asrc + (size_t)s * 4);
        den.x += __expf(lrelu(as.x + ad4.x));
        den.y += __expf(lrelu(as.y + ad4.y));
        den.z += __expf(lrelu(as.z + ad4.z));
        den.w += __expf(lrelu(as.w + ad4.w));
    }
    if (lane == 0) {  // self loop
        float4 as = *(const float4*)(g_asrc + (size_t)d * 4);
        den.x += __expf(lrelu(as.x + ad4.x));
        den.y += __expf(lrelu(as.y + ad4.y));
        den.z += __expf(lrelu(as.z + ad4.z));
        den.w += __expf(lrelu(as.w + ad4.w));
    }
#pragma unroll
    for (int off = 16; off; off >>= 1) {
        den.x += __shfl_xor_sync(0xFFFFFFFFu, den.x, off);
        den.y += __shfl_xor_sync(0xFFFFFFFFu, den.y, off);
        den.z += __shfl_xor_sync(0xFFFFFFFFu, den.z, off);
        den.w += __shfl_xor_sync(0xFFFFFFFFu, den.w, off);
    }
    const float inv = 1.0f / sel4(den, hh);
    const float adst_h = sel4(ad4, hh);

    // ---- pass 2: weighted gather, register accumulate
    float4 acc = make_float4(0.f, 0.f, 0.f, 0.f);
    for (int j = beg; j < end; j++) {
        int s = __ldg(&g_csrc[j]);
        float alpha = __expf(lrelu(__ldg(&g_asrc[(size_t)s * 4 + hh]) + adst_h)) * inv;
        float4 hv = ((const float4*)(g_h + (size_t)s * 128))[lane];
        acc.x = fmaf(hv.x, alpha, acc.x);
        acc.y = fmaf(hv.y, alpha, acc.y);
        acc.z = fmaf(hv.z, alpha, acc.z);
        acc.w = fmaf(hv.w, alpha, acc.w);
    }
    {   // self loop
        float alpha = __expf(lrelu(__ldg(&g_asrc[(size_t)d * 4 + hh]) + adst_h)) * inv;
        float4 hv = ((const float4*)(g_h + (size_t)d * 128))[lane];
        acc.x = fmaf(hv.x, alpha, acc.x);
        acc.y = fmaf(hv.y, alpha, acc.y);
        acc.z = fmaf(hv.z, alpha, acc.z);
        acc.w = fmaf(hv.w, alpha, acc.w);
    }

    float4 b4 = ((const float4*)bias)[lane];
    acc.x += b4.x; acc.y += b4.y; acc.z += b4.z; acc.w += b4.w;
    ((float4*)(out + (size_t)d * 128))[lane] = acc;
}

// ---------------------------------------------------------------------------
extern "C" void kernel_launch(void* const* d_in, const int* in_sizes, int n_in,
                              void* d_out, int out_size) {
    // Classify inputs by element count — robust to metadata ordering.
    int idx_W = -1;
    int small[3] = {-1, -1, -1}; int ns = 0;
    for (int i = 0; i < n_in; i++) {
        int sz = in_sizes[i];
        if (sz == 128 && ns < 3)  small[ns++] = i;
        else if (sz == 128 * 128) idx_W = i;
    }
    int idx_x = -1, idx_e = -1;
    for (int i = 0; i < n_in; i++) {
        if (in_sizes[i] == 128 || in_sizes[i] == 128 * 128) continue;
        if (idx_x < 0 || in_sizes[i] > in_sizes[idx_x]) { idx_e = idx_x; idx_x = i; }
        else if (idx_e < 0 || in_sizes[i] > in_sizes[idx_e]) { idx_e = i; }
    }
    int idx_asrc, idx_adst, idx_bias;
    if (idx_x < small[0]) {          // signature/dict order: att_src, att_dst, bias
        idx_asrc = small[0]; idx_adst = small[1]; idx_bias = small[2];
    } else {                         // alphabetical: att_dst, att_src, bias
        idx_adst = small[0]; idx_asrc = small[1]; idx_bias = small[2];
    }

    const float* x       = (const float*)d_in[idx_x];
    const void*  ei      = d_in[idx_e];
    const float* W       = (const float*)d_in[idx_W];
    const float* att_src = (const float*)d_in[idx_asrc];
    const float* att_dst = (const float*)d_in[idx_adst];
    const float* bias    = (const float*)d_in[idx_bias];
    float* out           = (float*)d_out;

    const int N = in_sizes[idx_x] / 128;
    const int E = in_sizes[idx_e] / 2;
    const int nb = (N + 1023) / 1024;   // scan blocks (98 for N=100k, <=256)

    k_detect<<<1, 1>>>(ei, N);

    // CSR build
    k_zero<<<(N + 256) / 256, 256>>>(N);
    k_hist<<<(E + 255) / 256, 256>>>(ei, E);
    k_scan1<<<nb, 1024>>>(N);
    k_scan2<<<1, 256>>>(nb);
    k_scan3<<<nb + 1, 1024>>>(N, E);    // +1 block guarantees i==N covered
    k_csr<<<(E + 255) / 256, 256>>>(ei, E);

    // GEMM + fused attention logits
    k_gemm<<<(N + 63) / 64, 256>>>(x, W, att_src, att_dst, N);

    // Per-dst softmax + aggregation (warp per node)
    {
        long long threads = (long long)N * 32;
        int blocks = (int)((threads + 255) / 256);
        k_agg<<<blocks, 256>>>(out, bias, N);
    }
}

// round 7
// speedup vs baseline: 2.0603x; 1.2110x over previous
#include <cuda_runtime.h>
#include <cuda_bf16.h>
#include <cstdint>

// Problem constants (dataset-fixed): N=100000, E=1600000, F=128, H=4, C=32
#define NMAX 100000
#define EMAX 1600000

// Scratch (device globals — allocation-free per harness rules)
__device__ __align__(16) float g_h[(size_t)NMAX * 128];    // 51.2 MB
__device__ __align__(16) float g_asrc[(size_t)NMAX * 4];
__device__ __align__(16) float g_adst[(size_t)NMAX * 4];
__device__ __align__(16) __nv_bfloat16 g_wtb_hi[128 * 128];  // W^T bf16 hi
__device__ __align__(16) __nv_bfloat16 g_wtb_lo[128 * 128];  // W^T bf16 lo
__device__ int g_deg[NMAX + 1];
__device__ int g_off[NMAX + 1];
__device__ int g_cur[NMAX];
__device__ int g_csrc[EMAX];
__device__ int g_bsum[256];
__device__ int g_bpre[256];
__device__ int g_is64;

__device__ __forceinline__ float sel4(float4 v, int h) {
    float a = (h & 1) ? v.y : v.x;
    float b = (h & 1) ? v.w : v.z;
    return (h & 2) ? b : a;
}
__device__ __forceinline__ float lrelu(float v) { return v > 0.f ? v : 0.2f * v; }
__device__ __forceinline__ float bf16r(float x) {
    return __bfloat162float(__float2bfloat16(x));
}
// pack two floats as bf16x2: lo element in low 16 bits
__device__ __forceinline__ uint32_t pack_bf2(float lo, float hi) {
    uint32_t r;
    asm("cvt.rn.bf16x2.f32 %0, %1, %2;" : "=r"(r) : "f"(hi), "f"(lo));
    return r;
}

__device__ __forceinline__ void mma_bf16(float* c, uint32_t a0, uint32_t a1,
                                         uint32_t a2, uint32_t a3,
                                         uint32_t b0, uint32_t b1) {
    asm volatile(
        "mma.sync.aligned.m16n8k16.row.col.f32.bf16.bf16.f32 "
        "{%0,%1,%2,%3}, {%4,%5,%6,%7}, {%8,%9}, {%0,%1,%2,%3};"
        : "+f"(c[0]), "+f"(c[1]), "+f"(c[2]), "+f"(c[3])
        : "r"(a0), "r"(a1), "r"(a2), "r"(a3), "r"(b0), "r"(b1));
}

// ---------------------------------------------------------------------------
// dtype probe
// ---------------------------------------------------------------------------
__global__ void k_detect(const void* ei, int N) {
    const long long* p = (const long long*)ei;
    bool ok64 = true;
#pragma unroll
    for (int i = 0; i < 8; i++) {
        long long v = p[i];
        if (v < 0 || v >= N) ok64 = false;
    }
    g_is64 = ok64 ? 1 : 0;
}
__device__ __forceinline__ int edge_src(const void* ei, int e) {
    return g_is64 ? (int)__ldg((const long long*)ei + e) : __ldg((const int*)ei + e);
}
__device__ __forceinline__ int edge_dst(const void* ei, int e, int E) {
    return g_is64 ? (int)__ldg((const long long*)ei + (size_t)E + e)
                  : __ldg((const int*)ei + (size_t)E + e);
}

// ---------------------------------------------------------------------------
// CSR build (unchanged from R5)
// ---------------------------------------------------------------------------
__global__ void k_zero(int N) {
    int i = blockIdx.x * blockDim.x + threadIdx.x;
    if (i <= N) g_deg[i] = 0;
}
__global__ void k_hist(const void* __restrict__ ei, int E) {
    int e = blockIdx.x * blockDim.x + threadIdx.x;
    if (e < E) atomicAdd(&g_deg[edge_dst(ei, e, E)], 1);
}
__global__ void __launch_bounds__(1024) k_scan1(int n) {
    __shared__ int warp_sums[32];
    const int tid = threadIdx.x, lane = tid & 31, wid = tid >> 5;
    int i = blockIdx.x * 1024 + tid;
    int v = (i < n) ? g_deg[i] : 0;
    int x = v;
#pragma unroll
    for (int off = 1; off < 32; off <<= 1) {
        int y = __shfl_up_sync(0xFFFFFFFFu, x, off);
        if (lane >= off) x += y;
    }
    if (lane == 31) warp_sums[wid] = x;
    __syncthreads();
    if (wid == 0) {
        int s = warp_sums[lane];
#pragma unroll
        for (int off = 1; off < 32; off <<= 1) {
            int y = __shfl_up_sync(0xFFFFFFFFu, s, off);
            if (lane >= off) s += y;
        }
        warp_sums[lane] = s;
    }
    __syncthreads();
    int incl = x + (wid ? warp_sums[wid - 1] : 0);
    if (i < n) g_off[i] = incl - v;
    if (tid == 1023) g_bsum[blockIdx.x] = incl;
}
__global__ void __launch_bounds__(256) k_scan2(int nb) {
    __shared__ int s[256];
    int tid = threadIdx.x;
    s[tid] = (tid < nb) ? g_bsum[tid] : 0;
    __syncthreads();
#pragma unroll
    for (int off = 1; off < 256; off <<= 1) {
        int v = (tid >= off) ? s[tid - off] : 0;
        __syncthreads();
        s[tid] += v;
        __syncthreads();
    }
    if (tid < nb) g_bpre[tid] = s[tid] - g_bsum[tid];
}
__global__ void __launch_bounds__(1024) k_scan3(int n, int E) {
    int i = blockIdx.x * 1024 + threadIdx.x;
    if (i < n) {
        int v = g_off[i] + g_bpre[blockIdx.x];
        g_off[i] = v;
        g_cur[i] = v;
    }
    if (i == n) g_off[n] = E;
}
__global__ void k_csr(const void* __restrict__ ei, int E) {
    int e = blockIdx.x * blockDim.x + threadIdx.x;
    if (e >= E) return;
    int s = edge_src(ei, e);
    int d = edge_dst(ei, e, E);
    int pos = atomicAdd(&g_cur[d], 1);
    g_csrc[pos] = s;
}

// ---------------------------------------------------------------------------
// W^T bf16 split precompute: g_wtb_hi/lo[n*128+k] from W[k*128+n]
// ---------------------------------------------------------------------------
__global__ void k_wt(const float* __restrict__ W) {
    int i = blockIdx.x * blockDim.x + threadIdx.x;
    if (i >= 128 * 128) return;
    int n = i >> 7, k = i & 127;
    float v = __ldg(W + k * 128 + n);
    float hi = bf16r(v);
    g_wtb_hi[i] = __float2bfloat16(v);
    g_wtb_lo[i] = __float2bfloat16(v - hi);
}

// ---------------------------------------------------------------------------
// GEMM via mma.sync m16n8k16 bf16, 3-term split (fp32-accurate).
// 128x128 tile/CTA, full K=128 in smem. 8 warps, warp tile 32m x 64n.
// Fused attention-logit epilogue (head = 32 cols, warp-local).
// ---------------------------------------------------------------------------
#define AS_STRIDE 136                       // padded bf16 row stride
#define SM_AHI 0
#define SM_ALO (128 * AS_STRIDE * 2)        // 34816
#define SM_BHI (SM_ALO + 128 * AS_STRIDE * 2)
#define SM_BLO (SM_BHI + 128 * AS_STRIDE * 2)
#define SM_ATT (SM_BLO + 128 * AS_STRIDE * 2)  // 139264: as[128] f32, ad[128] f32
#define SM_TOT (SM_ATT + 1024)                 // 140288

__global__ void __launch_bounds__(256, 1)
k_gemm_mma(const float* __restrict__ x,
           const float* __restrict__ att_src, const float* __restrict__ att_dst,
           int N) {
    extern __shared__ char smem[];
    const int tid = threadIdx.x;
    const int row0 = blockIdx.x * 128;

    // stage att vectors
    if (tid < 128)       *(float*)(smem + SM_ATT + tid * 4) = att_src[tid];
    else if (tid < 256)  *(float*)(smem + SM_ATT + 512 + (tid - 128) * 4) = att_dst[tid - 128];

    // ---- load + split A: 128 rows x 128 k (16 float4 per thread)
    const float4* Xg = (const float4*)x;
#pragma unroll
    for (int i = 0; i < 16; i++) {
        int idx = tid + i * 256;            // 0..4095
        int m = idx >> 5, kf4 = idx & 31;   // k = kf4*4
        int gr = row0 + m;
        float4 v = (gr < N) ? Xg[(size_t)gr * 32 + kf4]
                            : make_float4(0.f, 0.f, 0.f, 0.f);
        float hx = bf16r(v.x), hy = bf16r(v.y), hz = bf16r(v.z), hw = bf16r(v.w);
        uint2 hi2 = make_uint2(pack_bf2(hx, hy), pack_bf2(hz, hw));
        uint2 lo2 = make_uint2(pack_bf2(v.x - hx, v.y - hy),
                               pack_bf2(v.z - hz, v.w - hw));
        uint32_t off = (uint32_t)(m * AS_STRIDE + kf4 * 4) * 2;
        *(uint2*)(smem + SM_AHI + off) = hi2;
        *(uint2*)(smem + SM_ALO + off) = lo2;
    }
    // ---- load B (pre-split bf16 W^T): 128 n x 128 k, uint4 = 8 bf16
#pragma unroll
    for (int i = 0; i < 8; i++) {
        int idx = tid + i * 256;            // 0..2047
        int n = idx >> 4, kb = (idx & 15) * 8;
        uint32_t off = (uint32_t)(n * AS_STRIDE + kb) * 2;
        *(uint4*)(smem + SM_BHI + off) = *(const uint4*)(g_wtb_hi + n * 128 + kb);
        *(uint4*)(smem + SM_BLO + off) = *(const uint4*)(g_wtb_lo + n * 128 + kb);
    }
    __syncthreads();

    const int w = tid >> 5, lane = tid & 31;
    const int mw = w & 3, nw = w >> 2;
    const int m0 = mw * 32, n0 = nw * 64;
    const int g = lane >> 2, q = lane & 3;

    float acc[2][8][4];
#pragma unroll
    for (int a = 0; a < 2; a++)
#pragma unroll
        for (int b = 0; b < 8; b++)
#pragma unroll
            for (int c = 0; c < 4; c++) acc[a][b][c] = 0.f;

    const char* sA_hi = smem + SM_AHI;
    const char* sA_lo = smem + SM_ALO;
    const char* sB_hi = smem + SM_BHI;
    const char* sB_lo = smem + SM_BLO;

#pragma unroll
    for (int ka = 0; ka < 8; ka++) {
        const int k0 = ka * 16 + q * 2;
        uint32_t ah[2][4], al[2][4];
#pragma unroll
        for (int ma = 0; ma < 2; ma++) {
            int r = m0 + ma * 16 + g;
            uint32_t o00 = (uint32_t)(r * AS_STRIDE + k0) * 2;
            uint32_t o10 = (uint32_t)((r + 8) * AS_STRIDE + k0) * 2;
            ah[ma][0] = *(const uint32_t*)(sA_hi + o00);
            ah[ma][1] = *(const uint32_t*)(sA_hi + o10);
            ah[ma][2] = *(const uint32_t*)(sA_hi + o00 + 16);
            ah[ma][3] = *(const uint32_t*)(sA_hi + o10 + 16);
            al[ma][0] = *(const uint32_t*)(sA_lo + o00);
            al[ma][1] = *(const uint32_t*)(sA_lo + o10);
            al[ma][2] = *(const uint32_t*)(sA_lo + o00 + 16);
            al[ma][3] = *(const uint32_t*)(sA_lo + o10 + 16);
        }
        uint32_t bh[8][2], bl[8][2];
#pragma unroll
        for (int na = 0; na < 8; na++) {
            int n = n0 + na * 8 + g;
            uint32_t o = (uint32_t)(n * AS_STRIDE + k0) * 2;
            bh[na][0] = *(const uint32_t*)(sB_hi + o);
            bh[na][1] = *(const uint32_t*)(sB_hi + o + 16);
            bl[na][0] = *(const uint32_t*)(sB_lo + o);
            bl[na][1] = *(const uint32_t*)(sB_lo + o + 16);
        }
#pragma unroll
        for (int ma = 0; ma < 2; ma++)
#pragma unroll
            for (int na = 0; na < 8; na++) {
                mma_bf16(acc[ma][na], ah[ma][0], ah[ma][1], ah[ma][2], ah[ma][3],
                         bh[na][0], bh[na][1]);
                mma_bf16(acc[ma][na], ah[ma][0], ah[ma][1], ah[ma][2], ah[ma][3],
                         bl[na][0], bl[na][1]);
                mma_bf16(acc[ma][na], al[ma][0], al[ma][1], al[ma][2], al[ma][3],
                         bh[na][0], bh[na][1]);
            }
    }

    // ---- epilogue: write h rows + warp-local per-head logits
    const float* s_as = (const float*)(smem + SM_ATT);
    const float* s_ad = (const float*)(smem + SM_ATT + 512);

#pragma unroll
    for (int ma = 0; ma < 2; ma++) {
#pragma unroll
        for (int half = 0; half < 2; half++) {
            int row = row0 + m0 + ma * 16 + g + half * 8;
            float as0 = 0.f, as1 = 0.f, ad0 = 0.f, ad1 = 0.f;
#pragma unroll
            for (int na = 0; na < 8; na++) {
                int col = n0 + na * 8 + q * 2;
                float v0 = acc[ma][na][half * 2];
                float v1 = acc[ma][na][half * 2 + 1];
                if (row < N)
                    *(float2*)(g_h + (size_t)row * 128 + col) = make_float2(v0, v1);
                float ps = v0 * s_as[col] + v1 * s_as[col + 1];
                float pd = v0 * s_ad[col] + v1 * s_ad[col + 1];
                if (na < 4) { as0 += ps; ad0 += pd; }
                else        { as1 += ps; ad1 += pd; }
            }
            // quad reduce (lanes sharing g differ in low 2 bits)
#pragma unroll
            for (int off = 1; off < 4; off <<= 1) {
                as0 += __shfl_xor_sync(0xFFFFFFFFu, as0, off);
                as1 += __shfl_xor_sync(0xFFFFFFFFu, as1, off);
                ad0 += __shfl_xor_sync(0xFFFFFFFFu, ad0, off);
                ad1 += __shfl_xor_sync(0xFFFFFFFFu, ad1, off);
            }
            if (q == 0 && row < N) {
                int hb = nw * 2;
                g_asrc[(size_t)row * 4 + hb]     = as0;
                g_asrc[(size_t)row * 4 + hb + 1] = as1;
                g_adst[(size_t)row * 4 + hb]     = ad0;
                g_adst[(size_t)row * 4 + hb + 1] = ad1;
            }
        }
    }
}

// ---------------------------------------------------------------------------
// Aggregation (unchanged): warp/node, two-pass softmax+gather, zero atomics
// ---------------------------------------------------------------------------
__global__ void __launch_bounds__(256) k_agg(float* __restrict__ out,
                                             const float* __restrict__ bias,
                                             int N) {
    int d = (blockIdx.x * blockDim.x + threadIdx.x) >> 5;
    int lane = threadIdx.x & 31;
    if (d >= N) return;
    const int hh = lane >> 3;

    const float4 ad4 = *(const float4*)(g_adst + (size_t)d * 4);
    const int beg = g_off[d];
    const int end = g_off[d + 1];

    float4 den = make_float4(0.f, 0.f, 0.f, 0.f);
    for (int j = beg + lane; j < end; j += 32) {
        int s = __ldg(&g_csrc[j]);
        float4 as = *(const float4*)(g_asrc + (size_t)s * 4);
        den.x += __expf(lrelu(as.x + ad4.x));
        den.y += __expf(lrelu(as.y + ad4.y));
        den.z += __expf(lrelu(as.z + ad4.z));
        den.w += __expf(lrelu(as.w + ad4.w));
    }
    if (lane == 0) {
        float4 as = *(const float4*)(g_asrc + (size_t)d * 4);
        den.x += __expf(lrelu(as.x + ad4.x));
        den.y += __expf(lrelu(as.y + ad4.y));
        den.z += __expf(lrelu(as.z + ad4.z));
        den.w += __expf(lrelu(as.w + ad4.w));
    }
#pragma unroll
    for (int off = 16; off; off >>= 1) {
        den.x += __shfl_xor_sync(0xFFFFFFFFu, den.x, off);
        den.y += __shfl_xor_sync(0xFFFFFFFFu, den.y, off);
        den.z += __shfl_xor_sync(0xFFFFFFFFu, den.z, off);
        den.w += __shfl_xor_sync(0xFFFFFFFFu, den.w, off);
    }
    const float inv = 1.0f / sel4(den, hh);
    const float adst_h = sel4(ad4, hh);

    float4 acc = make_float4(0.f, 0.f, 0.f, 0.f);
    for (int j = beg; j < end; j++) {
        int s = __ldg(&g_csrc[j]);
        float alpha = __expf(lrelu(__ldg(&g_asrc[(size_t)s * 4 + hh]) + adst_h)) * inv;
        float4 hv = ((const float4*)(g_h + (size_t)s * 128))[lane];
        acc.x = fmaf(hv.x, alpha, acc.x);
        acc.y = fmaf(hv.y, alpha, acc.y);
        acc.z = fmaf(hv.z, alpha, acc.z);
        acc.w = fmaf(hv.w, alpha, acc.w);
    }
    {
        float alpha = __expf(lrelu(__ldg(&g_asrc[(size_t)d * 4 + hh]) + adst_h)) * inv;
        float4 hv = ((const float4*)(g_h + (size_t)d * 128))[lane];
        acc.x = fmaf(hv.x, alpha, acc.x);
        acc.y = fmaf(hv.y, alpha, acc.y);
        acc.z = fmaf(hv.z, alpha, acc.z);
        acc.w = fmaf(hv.w, alpha, acc.w);
    }

    float4 b4 = ((const float4*)bias)[lane];
    acc.x += b4.x; acc.y += b4.y; acc.z += b4.z; acc.w += b4.w;
    ((float4*)(out + (size_t)d * 128))[lane] = acc;
}

// ---------------------------------------------------------------------------
extern "C" void kernel_launch(void* const* d_in, const int* in_sizes, int n_in,
                              void* d_out, int out_size) {
    int idx_W = -1;
    int small[3] = {-1, -1, -1}; int ns = 0;
    for (int i = 0; i < n_in; i++) {
        int sz = in_sizes[i];
        if (sz == 128 && ns < 3)  small[ns++] = i;
        else if (sz == 128 * 128) idx_W = i;
    }
    int idx_x = -1, idx_e = -1;
    for (int i = 0; i < n_in; i++) {
        if (in_sizes[i] == 128 || in_sizes[i] == 128 * 128) continue;
        if (idx_x < 0 || in_sizes[i] > in_sizes[idx_x]) { idx_e = idx_x; idx_x = i; }
        else if (idx_e < 0 || in_sizes[i] > in_sizes[idx_e]) { idx_e = i; }
    }
    int idx_asrc, idx_adst, idx_bias;
    if (idx_x < small[0]) { idx_asrc = small[0]; idx_adst = small[1]; idx_bias = small[2]; }
    else                  { idx_adst = small[0]; idx_asrc = small[1]; idx_bias = small[2]; }

    const float* x       = (const float*)d_in[idx_x];
    const void*  ei      = d_in[idx_e];
    const float* W       = (const float*)d_in[idx_W];
    const float* att_src = (const float*)d_in[idx_asrc];
    const float* att_dst = (const float*)d_in[idx_adst];
    const float* bias    = (const float*)d_in[idx_bias];
    float* out           = (float*)d_out;

    const int N = in_sizes[idx_x] / 128;
    const int E = in_sizes[idx_e] / 2;
    const int nb = (N + 1023) / 1024;

    static int smem_set = 0;
    if (!smem_set) {
        cudaFuncSetAttribute(k_gemm_mma, cudaFuncAttributeMaxDynamicSharedMemorySize, SM_TOT);
        smem_set = 1;
    }

    k_detect<<<1, 1>>>(ei, N);

    // CSR build
    k_zero<<<(N + 256) / 256, 256>>>(N);
    k_hist<<<(E + 255) / 256, 256>>>(ei, E);
    k_scan1<<<nb, 1024>>>(N);
    k_scan2<<<1, 256>>>(nb);
    k_scan3<<<nb + 1, 1024>>>(N, E);
    k_csr<<<(E + 255) / 256, 256>>>(ei, E);

    // GEMM (tensor core mma.sync) + fused logits
    k_wt<<<(128 * 128 + 255) / 256, 256>>>(W);
    k_gemm_mma<<<(N + 127) / 128, 256, SM_TOT>>>(x, att_src, att_dst, N);

    // Aggregation
    {
        long long threads = (long long)N * 32;
        int blocks = (int)((threads + 255) / 256);
        k_agg<<<blocks, 256>>>(out, bias, N);
    }
}

// round 8
// speedup vs baseline: 2.4427x; 1.1856x over previous
#include <cuda_runtime.h>
#include <cuda_bf16.h>
#include <cstdint>

// Problem constants (dataset-fixed): N=100000, E=1600000, F=128, H=4, C=32
#define NMAX 100000
#define EMAX 1600000

// Scratch (device globals — allocation-free per harness rules)
__device__ __align__(16) float g_h[(size_t)NMAX * 128];    // 51.2 MB
__device__ __align__(16) float g_asrc[(size_t)NMAX * 4];
__device__ __align__(16) float g_adst[(size_t)NMAX * 4];
__device__ __align__(16) __nv_bfloat16 g_wtb_hi[128 * 128];  // W^T bf16 hi
__device__ __align__(16) __nv_bfloat16 g_wtb_lo[128 * 128];  // W^T bf16 lo
__device__ int g_deg[NMAX + 1];
__device__ int g_off[NMAX + 1];
__device__ int g_cur[NMAX];
__device__ int g_csrc[EMAX];
__device__ int g_bsum[256];
__device__ int g_bpre[256];
__device__ int g_is64;

__device__ __forceinline__ float lrelu(float v) { return v > 0.f ? v : 0.2f * v; }
__device__ __forceinline__ float bf16r(float x) {
    return __bfloat162float(__float2bfloat16(x));
}
__device__ __forceinline__ uint32_t pack_bf2(float lo, float hi) {
    uint32_t r;
    asm("cvt.rn.bf16x2.f32 %0, %1, %2;" : "=r"(r) : "f"(hi), "f"(lo));
    return r;
}
__device__ __forceinline__ void mma_bf16(float* c, uint32_t a0, uint32_t a1,
                                         uint32_t a2, uint32_t a3,
                                         uint32_t b0, uint32_t b1) {
    asm volatile(
        "mma.sync.aligned.m16n8k16.row.col.f32.bf16.bf16.f32 "
        "{%0,%1,%2,%3}, {%4,%5,%6,%7}, {%8,%9}, {%0,%1,%2,%3};"
        : "+f"(c[0]), "+f"(c[1]), "+f"(c[2]), "+f"(c[3])
        : "r"(a0), "r"(a1), "r"(a2), "r"(a3), "r"(b0), "r"(b1));
}

// ---------------------------------------------------------------------------
__global__ void k_detect(const void* ei, int N) {
    const long long* p = (const long long*)ei;
    bool ok64 = true;
#pragma unroll
    for (int i = 0; i < 8; i++) {
        long long v = p[i];
        if (v < 0 || v >= N) ok64 = false;
    }
    g_is64 = ok64 ? 1 : 0;
}
__device__ __forceinline__ int edge_src(const void* ei, int e) {
    return g_is64 ? (int)__ldg((const long long*)ei + e) : __ldg((const int*)ei + e);
}
__device__ __forceinline__ int edge_dst(const void* ei, int e, int E) {
    return g_is64 ? (int)__ldg((const long long*)ei + (size_t)E + e)
                  : __ldg((const int*)ei + (size_t)E + e);
}

// ---------------------------------------------------------------------------
// CSR build
// ---------------------------------------------------------------------------
__global__ void k_zero(int N) {
    int i = blockIdx.x * blockDim.x + threadIdx.x;
    if (i <= N) g_deg[i] = 0;
}
__global__ void k_hist(const void* __restrict__ ei, int E) {
    int e = blockIdx.x * blockDim.x + threadIdx.x;
    if (e < E) atomicAdd(&g_deg[edge_dst(ei, e, E)], 1);
}
__global__ void __launch_bounds__(1024) k_scan1(int n) {
    __shared__ int warp_sums[32];
    const int tid = threadIdx.x, lane = tid & 31, wid = tid >> 5;
    int i = blockIdx.x * 1024 + tid;
    int v = (i < n) ? g_deg[i] : 0;
    int x = v;
#pragma unroll
    for (int off = 1; off < 32; off <<= 1) {
        int y = __shfl_up_sync(0xFFFFFFFFu, x, off);
        if (lane >= off) x += y;
    }
    if (lane == 31) warp_sums[wid] = x;
    __syncthreads();
    if (wid == 0) {
        int s = warp_sums[lane];
#pragma unroll
        for (int off = 1; off < 32; off <<= 1) {
            int y = __shfl_up_sync(0xFFFFFFFFu, s, off);
            if (lane >= off) s += y;
        }
        warp_sums[lane] = s;
    }
    __syncthreads();
    int incl = x + (wid ? warp_sums[wid - 1] : 0);
    if (i < n) g_off[i] = incl - v;
    if (tid == 1023) g_bsum[blockIdx.x] = incl;
}
__global__ void __launch_bounds__(256) k_scan2(int nb) {
    __shared__ int s[256];
    int tid = threadIdx.x;
    s[tid] = (tid < nb) ? g_bsum[tid] : 0;
    __syncthreads();
#pragma unroll
    for (int off = 1; off < 256; off <<= 1) {
        int v = (tid >= off) ? s[tid - off] : 0;
        __syncthreads();
        s[tid] += v;
        __syncthreads();
    }
    if (tid < nb) g_bpre[tid] = s[tid] - g_bsum[tid];
}
__global__ void __launch_bounds__(1024) k_scan3(int n, int E) {
    int i = blockIdx.x * 1024 + threadIdx.x;
    if (i < n) {
        int v = g_off[i] + g_bpre[blockIdx.x];
        g_off[i] = v;
        g_cur[i] = v;
    }
    if (i == n) g_off[n] = E;
}
__global__ void k_csr(const void* __restrict__ ei, int E) {
    int e = blockIdx.x * blockDim.x + threadIdx.x;
    if (e >= E) return;
    int s = edge_src(ei, e);
    int d = edge_dst(ei, e, E);
    int pos = atomicAdd(&g_cur[d], 1);
    g_csrc[pos] = s;
}

// ---------------------------------------------------------------------------
// W^T bf16 split precompute
// ---------------------------------------------------------------------------
__global__ void k_wt(const float* __restrict__ W) {
    int i = blockIdx.x * blockDim.x + threadIdx.x;
    if (i >= 128 * 128) return;
    int n = i >> 7, k = i & 127;
    float v = __ldg(W + k * 128 + n);
    float hi = bf16r(v);
    g_wtb_hi[i] = __float2bfloat16(v);
    g_wtb_lo[i] = __float2bfloat16(v - hi);
}

// ---------------------------------------------------------------------------
// GEMM via mma.sync m16n8k16 bf16, 3-term split + fused logits (as R7)
// ---------------------------------------------------------------------------
#define AS_STRIDE 136
#define SM_AHI 0
#define SM_ALO (128 * AS_STRIDE * 2)
#define SM_BHI (SM_ALO + 128 * AS_STRIDE * 2)
#define SM_BLO (SM_BHI + 128 * AS_STRIDE * 2)
#define SM_ATT (SM_BLO + 128 * AS_STRIDE * 2)
#define SM_TOT (SM_ATT + 1024)

__global__ void __launch_bounds__(256, 1)
k_gemm_mma(const float* __restrict__ x,
           const float* __restrict__ att_src, const float* __restrict__ att_dst,
           int N) {
    extern __shared__ char smem[];
    const int tid = threadIdx.x;
    const int row0 = blockIdx.x * 128;

    if (tid < 128)       *(float*)(smem + SM_ATT + tid * 4) = att_src[tid];
    else if (tid < 256)  *(float*)(smem + SM_ATT + 512 + (tid - 128) * 4) = att_dst[tid - 128];

    const float4* Xg = (const float4*)x;
#pragma unroll
    for (int i = 0; i < 16; i++) {
        int idx = tid + i * 256;
        int m = idx >> 5, kf4 = idx & 31;
        int gr = row0 + m;
        float4 v = (gr < N) ? Xg[(size_t)gr * 32 + kf4]
                            : make_float4(0.f, 0.f, 0.f, 0.f);
        float hx = bf16r(v.x), hy = bf16r(v.y), hz = bf16r(v.z), hw = bf16r(v.w);
        uint2 hi2 = make_uint2(pack_bf2(hx, hy), pack_bf2(hz, hw));
        uint2 lo2 = make_uint2(pack_bf2(v.x - hx, v.y - hy),
                               pack_bf2(v.z - hz, v.w - hw));
        uint32_t off = (uint32_t)(m * AS_STRIDE + kf4 * 4) * 2;
        *(uint2*)(smem + SM_AHI + off) = hi2;
        *(uint2*)(smem + SM_ALO + off) = lo2;
    }
#pragma unroll
    for (int i = 0; i < 8; i++) {
        int idx = tid + i * 256;
        int n = idx >> 4, kb = (idx & 15) * 8;
        uint32_t off = (uint32_t)(n * AS_STRIDE + kb) * 2;
        *(uint4*)(smem + SM_BHI + off) = *(const uint4*)(g_wtb_hi + n * 128 + kb);
        *(uint4*)(smem + SM_BLO + off) = *(const uint4*)(g_wtb_lo + n * 128 + kb);
    }
    __syncthreads();

    const int w = tid >> 5, lane = tid & 31;
    const int mw = w & 3, nw = w >> 2;
    const int m0 = mw * 32, n0 = nw * 64;
    const int g = lane >> 2, q = lane & 3;

    float acc[2][8][4];
#pragma unroll
    for (int a = 0; a < 2; a++)
#pragma unroll
        for (int b = 0; b < 8; b++)
#pragma unroll
            for (int c = 0; c < 4; c++) acc[a][b][c] = 0.f;

    const char* sA_hi = smem + SM_AHI;
    const char* sA_lo = smem + SM_ALO;
    const char* sB_hi = smem + SM_BHI;
    const char* sB_lo = smem + SM_BLO;

#pragma unroll
    for (int ka = 0; ka < 8; ka++) {
        const int k0 = ka * 16 + q * 2;
        uint32_t ah[2][4], al[2][4];
#pragma unroll
        for (int ma = 0; ma < 2; ma++) {
            int r = m0 + ma * 16 + g;
            uint32_t o00 = (uint32_t)(r * AS_STRIDE + k0) * 2;
            uint32_t o10 = (uint32_t)((r + 8) * AS_STRIDE + k0) * 2;
            ah[ma][0] = *(const uint32_t*)(sA_hi + o00);
            ah[ma][1] = *(const uint32_t*)(sA_hi + o10);
            ah[ma][2] = *(const uint32_t*)(sA_hi + o00 + 16);
            ah[ma][3] = *(const uint32_t*)(sA_hi + o10 + 16);
            al[ma][0] = *(const uint32_t*)(sA_lo + o00);
            al[ma][1] = *(const uint32_t*)(sA_lo + o10);
            al[ma][2] = *(const uint32_t*)(sA_lo + o00 + 16);
            al[ma][3] = *(const uint32_t*)(sA_lo + o10 + 16);
        }
        uint32_t bh[8][2], bl[8][2];
#pragma unroll
        for (int na = 0; na < 8; na++) {
            int n = n0 + na * 8 + g;
            uint32_t o = (uint32_t)(n * AS_STRIDE + k0) * 2;
            bh[na][0] = *(const uint32_t*)(sB_hi + o);
            bh[na][1] = *(const uint32_t*)(sB_hi + o + 16);
            bl[na][0] = *(const uint32_t*)(sB_lo + o);
            bl[na][1] = *(const uint32_t*)(sB_lo + o + 16);
        }
#pragma unroll
        for (int ma = 0; ma < 2; ma++)
#pragma unroll
            for (int na = 0; na < 8; na++) {
                mma_bf16(acc[ma][na], ah[ma][0], ah[ma][1], ah[ma][2], ah[ma][3],
                         bh[na][0], bh[na][1]);
                mma_bf16(acc[ma][na], ah[ma][0], ah[ma][1], ah[ma][2], ah[ma][3],
                         bl[na][0], bl[na][1]);
                mma_bf16(acc[ma][na], al[ma][0], al[ma][1], al[ma][2], al[ma][3],
                         bh[na][0], bh[na][1]);
            }
    }

    const float* s_as = (const float*)(smem + SM_ATT);
    const float* s_ad = (const float*)(smem + SM_ATT + 512);

#pragma unroll
    for (int ma = 0; ma < 2; ma++) {
#pragma unroll
        for (int half = 0; half < 2; half++) {
            int row = row0 + m0 + ma * 16 + g + half * 8;
            float as0 = 0.f, as1 = 0.f, ad0 = 0.f, ad1 = 0.f;
#pragma unroll
            for (int na = 0; na < 8; na++) {
                int col = n0 + na * 8 + q * 2;
                float v0 = acc[ma][na][half * 2];
                float v1 = acc[ma][na][half * 2 + 1];
                if (row < N)
                    *(float2*)(g_h + (size_t)row * 128 + col) = make_float2(v0, v1);
                float ps = v0 * s_as[col] + v1 * s_as[col + 1];
                float pd = v0 * s_ad[col] + v1 * s_ad[col + 1];
                if (na < 4) { as0 += ps; ad0 += pd; }
                else        { as1 += ps; ad1 += pd; }
            }
#pragma unroll
            for (int off = 1; off < 4; off <<= 1) {
                as0 += __shfl_xor_sync(0xFFFFFFFFu, as0, off);
                as1 += __shfl_xor_sync(0xFFFFFFFFu, as1, off);
                ad0 += __shfl_xor_sync(0xFFFFFFFFu, ad0, off);
                ad1 += __shfl_xor_sync(0xFFFFFFFFu, ad1, off);
            }
            if (q == 0 && row < N) {
                int hb = nw * 2;
                g_asrc[(size_t)row * 4 + hb]     = as0;
                g_asrc[(size_t)row * 4 + hb + 1] = as1;
                g_adst[(size_t)row * 4 + hb]     = ad0;
                g_adst[(size_t)row * 4 + hb + 1] = ad1;
            }
        }
    }
}

// ---------------------------------------------------------------------------
// Aggregation: SINGLE pass. out = (sum_j p_j h_j) / (sum_j p_j) + bias.
// Each lane walks the full neighbor list: den computed redundantly per lane
// (no reduce), acc in registers, one plain 512B store. Zero atomics.
// ---------------------------------------------------------------------------
__global__ void __launch_bounds__(256) k_agg(float* __restrict__ out,
                                             const float* __restrict__ bias,
                                             int N) {
    int d = (blockIdx.x * blockDim.x + threadIdx.x) >> 5;
    int lane = threadIdx.x & 31;
    if (d >= N) return;
    const int hh = lane >> 3;

    const float adst_h = __ldg(&g_adst[(size_t)d * 4 + hh]);
    const int beg = g_off[d];
    const int end = g_off[d + 1];

    // self loop seeds the accumulators
    float den = __expf(lrelu(__ldg(&g_asrc[(size_t)d * 4 + hh]) + adst_h));
    float4 hv = ((const float4*)(g_h + (size_t)d * 128))[lane];
    float4 acc = make_float4(den * hv.x, den * hv.y, den * hv.z, den * hv.w);

#pragma unroll 2
    for (int j = beg; j < end; j++) {
        int s = __ldg(&g_csrc[j]);
        float p = __expf(lrelu(__ldg(&g_asrc[(size_t)s * 4 + hh]) + adst_h));
        den += p;
        float4 h2 = ((const float4*)(g_h + (size_t)s * 128))[lane];
        acc.x = fmaf(p, h2.x, acc.x);
        acc.y = fmaf(p, h2.y, acc.y);
        acc.z = fmaf(p, h2.z, acc.z);
        acc.w = fmaf(p, h2.w, acc.w);
    }

    const float inv = __fdividef(1.0f, den);
    float4 b4 = ((const float4*)bias)[lane];
    acc.x = fmaf(acc.x, inv, b4.x);
    acc.y = fmaf(acc.y, inv, b4.y);
    acc.z = fmaf(acc.z, inv, b4.z);
    acc.w = fmaf(acc.w, inv, b4.w);
    ((float4*)(out + (size_t)d * 128))[lane] = acc;
}

// ---------------------------------------------------------------------------
extern "C" void kernel_launch(void* const* d_in, const int* in_sizes, int n_in,
                              void* d_out, int out_size) {
    int idx_W = -1;
    int small[3] = {-1, -1, -1}; int ns = 0;
    for (int i = 0; i < n_in; i++) {
        int sz = in_sizes[i];
        if (sz == 128 && ns < 3)  small[ns++] = i;
        else if (sz == 128 * 128) idx_W = i;
    }
    int idx_x = -1, idx_e = -1;
    for (int i = 0; i < n_in; i++) {
        if (in_sizes[i] == 128 || in_sizes[i] == 128 * 128) continue;
        if (idx_x < 0 || in_sizes[i] > in_sizes[idx_x]) { idx_e = idx_x; idx_x = i; }
        else if (idx_e < 0 || in_sizes[i] > in_sizes[idx_e]) { idx_e = i; }
    }
    int idx_asrc, idx_adst, idx_bias;
    if (idx_x < small[0]) { idx_asrc = small[0]; idx_adst = small[1]; idx_bias = small[2]; }
    else                  { idx_adst = small[0]; idx_asrc = small[1]; idx_bias = small[2]; }

    const float* x       = (const float*)d_in[idx_x];
    const void*  ei      = d_in[idx_e];
    const float* W       = (const float*)d_in[idx_W];
    const float* att_src = (const float*)d_in[idx_asrc];
    const float* att_dst = (const float*)d_in[idx_adst];
    const float* bias    = (const float*)d_in[idx_bias];
    float* out           = (float*)d_out;

    const int N = in_sizes[idx_x] / 128;
    const int E = in_sizes[idx_e] / 2;
    const int nb = (N + 1023) / 1024;

    // One-time setup (first call is the uncaptured correctness run)
    static cudaStream_t s2 = nullptr;
    static cudaEvent_t evFork = nullptr, evJoin = nullptr;
    if (!s2) {
        cudaFuncSetAttribute(k_gemm_mma, cudaFuncAttributeMaxDynamicSharedMemorySize, SM_TOT);
        cudaStreamCreateWithFlags(&s2, cudaStreamNonBlocking);
        cudaEventCreateWithFlags(&evFork, cudaEventDisableTiming);
        cudaEventCreateWithFlags(&evJoin, cudaEventDisableTiming);
    }

    // Fork: CSR chain on s2, GEMM chain on the capture (default) stream
    cudaEventRecord(evFork, 0);
    cudaStreamWaitEvent(s2, evFork, 0);

    // --- s2: CSR build
    k_detect<<<1, 1, 0, s2>>>(ei, N);
    k_zero<<<(N + 256) / 256, 256, 0, s2>>>(N);
    k_hist<<<(E + 255) / 256, 256, 0, s2>>>(ei, E);
    k_scan1<<<nb, 1024, 0, s2>>>(N);
    k_scan2<<<1, 256, 0, s2>>>(nb);
    k_scan3<<<nb + 1, 1024, 0, s2>>>(N, E);
    k_csr<<<(E + 255) / 256, 256, 0, s2>>>(ei, E);

    // --- default stream: GEMM (tensor core) + fused logits
    k_wt<<<(128 * 128 + 255) / 256, 256>>>(W);
    k_gemm_mma<<<(N + 127) / 128, 256, SM_TOT>>>(x, att_src, att_dst, N);

    // Join, then aggregate
    cudaEventRecord(evJoin, s2);
    cudaStreamWaitEvent(0, evJoin, 0);
    {
        long long threads = (long long)N * 32;
        int blocks = (int)((threads + 255) / 256);
        k_agg<<<blocks, 256>>>(out, bias, N);
    }
}

// round 9
// speedup vs baseline: 2.4769x; 1.0140x over previous
#include <cuda_runtime.h>
#include <cuda_bf16.h>
#include <cuda_fp16.h>
#include <cstdint>

// Problem constants (dataset-fixed): N=100000, E=1600000, F=128, H=4, C=32
#define NMAX 100000
#define EMAX 1600000

// Scratch (device globals — allocation-free per harness rules)
__device__ __align__(16) __half g_hf[(size_t)NMAX * 128];  // 25.6 MB, fp16 h
__device__ __align__(16) float g_asrc[(size_t)NMAX * 4];
__device__ __align__(16) float g_adst[(size_t)NMAX * 4];
__device__ __align__(16) __nv_bfloat16 g_wtb_hi[128 * 128];
__device__ __align__(16) __nv_bfloat16 g_wtb_lo[128 * 128];
__device__ int g_deg[NMAX + 1];
__device__ int g_off[NMAX + 1];
__device__ int g_cur[NMAX];
__device__ int g_csrc[EMAX];
__device__ int g_bsum[256];
__device__ int g_bpre[256];
__device__ int g_is64;

__device__ __forceinline__ float lrelu(float v) { return v > 0.f ? v : 0.2f * v; }
__device__ __forceinline__ float bf16r(float x) {
    return __bfloat162float(__float2bfloat16(x));
}
__device__ __forceinline__ uint32_t pack_bf2(float lo, float hi) {
    uint32_t r;
    asm("cvt.rn.bf16x2.f32 %0, %1, %2;" : "=r"(r) : "f"(hi), "f"(lo));
    return r;
}
__device__ __forceinline__ void mma_bf16(float* c, uint32_t a0, uint32_t a1,
                                         uint32_t a2, uint32_t a3,
                                         uint32_t b0, uint32_t b1) {
    asm volatile(
        "mma.sync.aligned.m16n8k16.row.col.f32.bf16.bf16.f32 "
        "{%0,%1,%2,%3}, {%4,%5,%6,%7}, {%8,%9}, {%0,%1,%2,%3};"
        : "+f"(c[0]), "+f"(c[1]), "+f"(c[2]), "+f"(c[3])
        : "r"(a0), "r"(a1), "r"(a2), "r"(a3), "r"(b0), "r"(b1));
}

// ---------------------------------------------------------------------------
__global__ void k_detect(const void* ei, int N) {
    const long long* p = (const long long*)ei;
    bool ok64 = true;
#pragma unroll
    for (int i = 0; i < 8; i++) {
        long long v = p[i];
        if (v < 0 || v >= N) ok64 = false;
    }
    g_is64 = ok64 ? 1 : 0;
}
__device__ __forceinline__ int edge_src(const void* ei, int e) {
    return g_is64 ? (int)__ldg((const long long*)ei + e) : __ldg((const int*)ei + e);
}
__device__ __forceinline__ int edge_dst(const void* ei, int e, int E) {
    return g_is64 ? (int)__ldg((const long long*)ei + (size_t)E + e)
                  : __ldg((const int*)ei + (size_t)E + e);
}

// ---------------------------------------------------------------------------
// CSR build
// ---------------------------------------------------------------------------
__global__ void k_zero(int N) {
    int i = blockIdx.x * blockDim.x + threadIdx.x;
    if (i <= N) g_deg[i] = 0;
}
__global__ void k_hist(const void* __restrict__ ei, int E) {
    int e = blockIdx.x * blockDim.x + threadIdx.x;
    if (e < E) atomicAdd(&g_deg[edge_dst(ei, e, E)], 1);
}
__global__ void __launch_bounds__(1024) k_scan1(int n) {
    __shared__ int warp_sums[32];
    const int tid = threadIdx.x, lane = tid & 31, wid = tid >> 5;
    int i = blockIdx.x * 1024 + tid;
    int v = (i < n) ? g_deg[i] : 0;
    int x = v;
#pragma unroll
    for (int off = 1; off < 32; off <<= 1) {
        int y = __shfl_up_sync(0xFFFFFFFFu, x, off);
        if (lane >= off) x += y;
    }
    if (lane == 31) warp_sums[wid] = x;
    __syncthreads();
    if (wid == 0) {
        int s = warp_sums[lane];
#pragma unroll
        for (int off = 1; off < 32; off <<= 1) {
            int y = __shfl_up_sync(0xFFFFFFFFu, s, off);
            if (lane >= off) s += y;
        }
        warp_sums[lane] = s;
    }
    __syncthreads();
    int incl = x + (wid ? warp_sums[wid - 1] : 0);
    if (i < n) g_off[i] = incl - v;
    if (tid == 1023) g_bsum[blockIdx.x] = incl;
}
__global__ void __launch_bounds__(256) k_scan2(int nb) {
    __shared__ int s[256];
    int tid = threadIdx.x;
    s[tid] = (tid < nb) ? g_bsum[tid] : 0;
    __syncthreads();
#pragma unroll
    for (int off = 1; off < 256; off <<= 1) {
        int v = (tid >= off) ? s[tid - off] : 0;
        __syncthreads();
        s[tid] += v;
        __syncthreads();
    }
    if (tid < nb) g_bpre[tid] = s[tid] - g_bsum[tid];
}
__global__ void __launch_bounds__(1024) k_scan3(int n, int E) {
    int i = blockIdx.x * 1024 + threadIdx.x;
    if (i < n) {
        int v = g_off[i] + g_bpre[blockIdx.x];
        g_off[i] = v;
        g_cur[i] = v;
    }
    if (i == n) g_off[n] = E;
}
__global__ void k_csr(const void* __restrict__ ei, int E) {
    int e = blockIdx.x * blockDim.x + threadIdx.x;
    if (e >= E) return;
    int s = edge_src(ei, e);
    int d = edge_dst(ei, e, E);
    int pos = atomicAdd(&g_cur[d], 1);
    g_csrc[pos] = s;
}

// ---------------------------------------------------------------------------
// W^T bf16 split precompute
// ---------------------------------------------------------------------------
__global__ void k_wt(const float* __restrict__ W) {
    int i = blockIdx.x * blockDim.x + threadIdx.x;
    if (i >= 128 * 128) return;
    int n = i >> 7, k = i & 127;
    float v = __ldg(W + k * 128 + n);
    float hi = bf16r(v);
    g_wtb_hi[i] = __float2bfloat16(v);
    g_wtb_lo[i] = __float2bfloat16(v - hi);
}

// ---------------------------------------------------------------------------
// GEMM via mma.sync m16n8k16 bf16, 3-term split + fused logits.
// Epilogue writes fp16 h (g_hf) + fp32 logits.
// ---------------------------------------------------------------------------
#define AS_STRIDE 136
#define SM_AHI 0
#define SM_ALO (128 * AS_STRIDE * 2)
#define SM_BHI (SM_ALO + 128 * AS_STRIDE * 2)
#define SM_BLO (SM_BHI + 128 * AS_STRIDE * 2)
#define SM_ATT (SM_BLO + 128 * AS_STRIDE * 2)
#define SM_TOT (SM_ATT + 1024)

__global__ void __launch_bounds__(256, 1)
k_gemm_mma(const float* __restrict__ x,
           const float* __restrict__ att_src, const float* __restrict__ att_dst,
           int N) {
    extern __shared__ char smem[];
    const int tid = threadIdx.x;
    const int row0 = blockIdx.x * 128;

    if (tid < 128)       *(float*)(smem + SM_ATT + tid * 4) = att_src[tid];
    else if (tid < 256)  *(float*)(smem + SM_ATT + 512 + (tid - 128) * 4) = att_dst[tid - 128];

    const float4* Xg = (const float4*)x;
#pragma unroll
    for (int i = 0; i < 16; i++) {
        int idx = tid + i * 256;
        int m = idx >> 5, kf4 = idx & 31;
        int gr = row0 + m;
        float4 v = (gr < N) ? Xg[(size_t)gr * 32 + kf4]
                            : make_float4(0.f, 0.f, 0.f, 0.f);
        float hx = bf16r(v.x), hy = bf16r(v.y), hz = bf16r(v.z), hw = bf16r(v.w);
        uint2 hi2 = make_uint2(pack_bf2(hx, hy), pack_bf2(hz, hw));
        uint2 lo2 = make_uint2(pack_bf2(v.x - hx, v.y - hy),
                               pack_bf2(v.z - hz, v.w - hw));
        uint32_t off = (uint32_t)(m * AS_STRIDE + kf4 * 4) * 2;
        *(uint2*)(smem + SM_AHI + off) = hi2;
        *(uint2*)(smem + SM_ALO + off) = lo2;
    }
#pragma unroll
    for (int i = 0; i < 8; i++) {
        int idx = tid + i * 256;
        int n = idx >> 4, kb = (idx & 15) * 8;
        uint32_t off = (uint32_t)(n * AS_STRIDE + kb) * 2;
        *(uint4*)(smem + SM_BHI + off) = *(const uint4*)(g_wtb_hi + n * 128 + kb);
        *(uint4*)(smem + SM_BLO + off) = *(const uint4*)(g_wtb_lo + n * 128 + kb);
    }
    __syncthreads();

    const int w = tid >> 5, lane = tid & 31;
    const int mw = w & 3, nw = w >> 2;
    const int m0 = mw * 32, n0 = nw * 64;
    const int g = lane >> 2, q = lane & 3;

    float acc[2][8][4];
#pragma unroll
    for (int a = 0; a < 2; a++)
#pragma unroll
        for (int b = 0; b < 8; b++)
#pragma unroll
            for (int c = 0; c < 4; c++) acc[a][b][c] = 0.f;

    const char* sA_hi = smem + SM_AHI;
    const char* sA_lo = smem + SM_ALO;
    const char* sB_hi = smem + SM_BHI;
    const char* sB_lo = smem + SM_BLO;

#pragma unroll
    for (int ka = 0; ka < 8; ka++) {
        const int k0 = ka * 16 + q * 2;
        uint32_t ah[2][4], al[2][4];
#pragma unroll
        for (int ma = 0; ma < 2; ma++) {
            int r = m0 + ma * 16 + g;
            uint32_t o00 = (uint32_t)(r * AS_STRIDE + k0) * 2;
            uint32_t o10 = (uint32_t)((r + 8) * AS_STRIDE + k0) * 2;
            ah[ma][0] = *(const uint32_t*)(sA_hi + o00);
            ah[ma][1] = *(const uint32_t*)(sA_hi + o10);
            ah[ma][2] = *(const uint32_t*)(sA_hi + o00 + 16);
            ah[ma][3] = *(const uint32_t*)(sA_hi + o10 + 16);
            al[ma][0] = *(const uint32_t*)(sA_lo + o00);
            al[ma][1] = *(const uint32_t*)(sA_lo + o10);
            al[ma][2] = *(const uint32_t*)(sA_lo + o00 + 16);
            al[ma][3] = *(const uint32_t*)(sA_lo + o10 + 16);
        }
        uint32_t bh[8][2], bl[8][2];
#pragma unroll
        for (int na = 0; na < 8; na++) {
            int n = n0 + na * 8 + g;
            uint32_t o = (uint32_t)(n * AS_STRIDE + k0) * 2;
            bh[na][0] = *(const uint32_t*)(sB_hi + o);
            bh[na][1] = *(const uint32_t*)(sB_hi + o + 16);
            bl[na][0] = *(const uint32_t*)(sB_lo + o);
            bl[na][1] = *(const uint32_t*)(sB_lo + o + 16);
        }
#pragma unroll
        for (int ma = 0; ma < 2; ma++)
#pragma unroll
            for (int na = 0; na < 8; na++) {
                mma_bf16(acc[ma][na], ah[ma][0], ah[ma][1], ah[ma][2], ah[ma][3],
                         bh[na][0], bh[na][1]);
                mma_bf16(acc[ma][na], ah[ma][0], ah[ma][1], ah[ma][2], ah[ma][3],
                         bl[na][0], bl[na][1]);
                mma_bf16(acc[ma][na], al[ma][0], al[ma][1], al[ma][2], al[ma][3],
                         bh[na][0], bh[na][1]);
            }
    }

    const float* s_as = (const float*)(smem + SM_ATT);
    const float* s_ad = (const float*)(smem + SM_ATT + 512);

#pragma unroll
    for (int ma = 0; ma < 2; ma++) {
#pragma unroll
        for (int half = 0; half < 2; half++) {
            int row = row0 + m0 + ma * 16 + g + half * 8;
            float as0 = 0.f, as1 = 0.f, ad0 = 0.f, ad1 = 0.f;
#pragma unroll
            for (int na = 0; na < 8; na++) {
                int col = n0 + na * 8 + q * 2;
                float v0 = acc[ma][na][half * 2];
                float v1 = acc[ma][na][half * 2 + 1];
                if (row < N)
                    *(__half2*)(g_hf + (size_t)row * 128 + col) =
                        __floats2half2_rn(v0, v1);
                float ps = v0 * s_as[col] + v1 * s_as[col + 1];
                float pd = v0 * s_ad[col] + v1 * s_ad[col + 1];
                if (na < 4) { as0 += ps; ad0 += pd; }
                else        { as1 += ps; ad1 += pd; }
            }
#pragma unroll
            for (int off = 1; off < 4; off <<= 1) {
                as0 += __shfl_xor_sync(0xFFFFFFFFu, as0, off);
                as1 += __shfl_xor_sync(0xFFFFFFFFu, as1, off);
                ad0 += __shfl_xor_sync(0xFFFFFFFFu, ad0, off);
                ad1 += __shfl_xor_sync(0xFFFFFFFFu, ad1, off);
            }
            if (q == 0 && row < N) {
                int hb = nw * 2;
                g_asrc[(size_t)row * 4 + hb]     = as0;
                g_asrc[(size_t)row * 4 + hb + 1] = as1;
                g_adst[(size_t)row * 4 + hb]     = ad0;
                g_adst[(size_t)row * 4 + hb + 1] = ad1;
            }
        }
    }
}

// ---------------------------------------------------------------------------
// Aggregation: single pass, fp16 h gather (256B/row/warp). Zero atomics.
// out = (sum_j p_j h_j) / (sum_j p_j) + bias, softmax weights in fp32.
// ---------------------------------------------------------------------------
__global__ void __launch_bounds__(256) k_agg(float* __restrict__ out,
                                             const float* __restrict__ bias,
                                             int N) {
    int d = (blockIdx.x * blockDim.x + threadIdx.x) >> 5;
    int lane = threadIdx.x & 31;
    if (d >= N) return;
    const int hh = lane >> 3;

    const float adst_h = __ldg(&g_adst[(size_t)d * 4 + hh]);
    const int beg = g_off[d];
    const int end = g_off[d + 1];

    // self loop seeds the accumulators
    float den = __expf(lrelu(__ldg(&g_asrc[(size_t)d * 4 + hh]) + adst_h));
    float4 acc;
    {
        uint2 u = __ldg((const uint2*)(g_hf + (size_t)d * 128) + lane);
        float2 f0 = __half22float2(*(__half2*)&u.x);
        float2 f1 = __half22float2(*(__half2*)&u.y);
        acc = make_float4(den * f0.x, den * f0.y, den * f1.x, den * f1.y);
    }

#pragma unroll 2
    for (int j = beg; j < end; j++) {
        int s = __ldg(&g_csrc[j]);
        float p = __expf(lrelu(__ldg(&g_asrc[(size_t)s * 4 + hh]) + adst_h));
        den += p;
        uint2 u = __ldg((const uint2*)(g_hf + (size_t)s * 128) + lane);
        float2 f0 = __half22float2(*(__half2*)&u.x);
        float2 f1 = __half22float2(*(__half2*)&u.y);
        acc.x = fmaf(p, f0.x, acc.x);
        acc.y = fmaf(p, f0.y, acc.y);
        acc.z = fmaf(p, f1.x, acc.z);
        acc.w = fmaf(p, f1.y, acc.w);
    }

    const float inv = __fdividef(1.0f, den);
    float4 b4 = ((const float4*)bias)[lane];
    acc.x = fmaf(acc.x, inv, b4.x);
    acc.y = fmaf(acc.y, inv, b4.y);
    acc.z = fmaf(acc.z, inv, b4.z);
    acc.w = fmaf(acc.w, inv, b4.w);
    ((float4*)(out + (size_t)d * 128))[lane] = acc;
}

// ---------------------------------------------------------------------------
extern "C" void kernel_launch(void* const* d_in, const int* in_sizes, int n_in,
                              void* d_out, int out_size) {
    int idx_W = -1;
    int small[3] = {-1, -1, -1}; int ns = 0;
    for (int i = 0; i < n_in; i++) {
        int sz = in_sizes[i];
        if (sz == 128 && ns < 3)  small[ns++] = i;
        else if (sz == 128 * 128) idx_W = i;
    }
    int idx_x = -1, idx_e = -1;
    for (int i = 0; i < n_in; i++) {
        if (in_sizes[i] == 128 || in_sizes[i] == 128 * 128) continue;
        if (idx_x < 0 || in_sizes[i] > in_sizes[idx_x]) { idx_e = idx_x; idx_x = i; }
        else if (idx_e < 0 || in_sizes[i] > in_sizes[idx_e]) { idx_e = i; }
    }
    int idx_asrc, idx_adst, idx_bias;
    if (idx_x < small[0]) { idx_asrc = small[0]; idx_adst = small[1]; idx_bias = small[2]; }
    else                  { idx_adst = small[0]; idx_asrc = small[1]; idx_bias = small[2]; }

    const float* x       = (const float*)d_in[idx_x];
    const void*  ei      = d_in[idx_e];
    const float* W       = (const float*)d_in[idx_W];
    const float* att_src = (const float*)d_in[idx_asrc];
    const float* att_dst = (const float*)d_in[idx_adst];
    const float* bias    = (const float*)d_in[idx_bias];
    float* out           = (float*)d_out;

    const int N = in_sizes[idx_x] / 128;
    const int E = in_sizes[idx_e] / 2;
    const int nb = (N + 1023) / 1024;

    static cudaStream_t s2 = nullptr;
    static cudaEvent_t evFork = nullptr, evJoin = nullptr;
    if (!s2) {
        cudaFuncSetAttribute(k_gemm_mma, cudaFuncAttributeMaxDynamicSharedMemorySize, SM_TOT);
        cudaStreamCreateWithFlags(&s2, cudaStreamNonBlocking);
        cudaEventCreateWithFlags(&evFork, cudaEventDisableTiming);
        cudaEventCreateWithFlags(&evJoin, cudaEventDisableTiming);
    }

    cudaEventRecord(evFork, 0);
    cudaStreamWaitEvent(s2, evFork, 0);

    // --- s2: CSR build
    k_detect<<<1, 1, 0, s2>>>(ei, N);
    k_zero<<<(N + 256) / 256, 256, 0, s2>>>(N);
    k_hist<<<(E + 255) / 256, 256, 0, s2>>>(ei, E);
    k_scan1<<<nb, 1024, 0, s2>>>(N);
    k_scan2<<<1, 256, 0, s2>>>(nb);
    k_scan3<<<nb + 1, 1024, 0, s2>>>(N, E);
    k_csr<<<(E + 255) / 256, 256, 0, s2>>>(ei, E);

    // --- default stream: GEMM (tensor core) + fused logits
    k_wt<<<(128 * 128 + 255) / 256, 256>>>(W);
    k_gemm_mma<<<(N + 127) / 128, 256, SM_TOT>>>(x, att_src, att_dst, N);

    // Join, then aggregate
    cudaEventRecord(evJoin, s2);
    cudaStreamWaitEvent(0, evJoin, 0);
    {
        long long threads = (long long)N * 32;
        int blocks = (int)((threads + 255) / 256);
        k_agg<<<blocks, 256>>>(out, bias, N);
    }
}

// round 10
// speedup vs baseline: 2.5947x; 1.0476x over previous
#include <cuda_runtime.h>
#include <cuda_bf16.h>
#include <cuda_fp16.h>
#include <cstdint>

// Problem constants (dataset-fixed): N=100000, E=1600000, F=128, H=4, C=32
#define NMAX 100000
#define EMAX 1600000

// Scratch (device globals — allocation-free per harness rules)
__device__ __align__(16) __half g_hf[(size_t)NMAX * 128];  // 25.6 MB, fp16 h
__device__ __align__(16) float g_asrc[(size_t)NMAX * 4];
__device__ __align__(16) float g_adst[(size_t)NMAX * 4];
__device__ __align__(16) __nv_bfloat16 g_wtb_hi[128 * 128];
__device__ __align__(16) __nv_bfloat16 g_wtb_lo[128 * 128];
__device__ int g_deg[NMAX + 1];
__device__ int g_off[NMAX + 1];
__device__ int g_cur[NMAX];
__device__ int g_csrc[EMAX];
__device__ int g_bsum[256];
__device__ int g_bpre[256];
__device__ int g_is64;

__device__ __forceinline__ float sel4(float4 v, int h) {
    float a = (h & 1) ? v.y : v.x;
    float b = (h & 1) ? v.w : v.z;
    return (h & 2) ? b : a;
}
__device__ __forceinline__ float lrelu(float v) { return v > 0.f ? v : 0.2f * v; }
__device__ __forceinline__ float bf16r(float x) {
    return __bfloat162float(__float2bfloat16(x));
}
__device__ __forceinline__ uint32_t pack_bf2(float lo, float hi) {
    uint32_t r;
    asm("cvt.rn.bf16x2.f32 %0, %1, %2;" : "=r"(r) : "f"(hi), "f"(lo));
    return r;
}
__device__ __forceinline__ void mma_bf16(float* c, uint32_t a0, uint32_t a1,
                                         uint32_t a2, uint32_t a3,
                                         uint32_t b0, uint32_t b1) {
    asm volatile(
        "mma.sync.aligned.m16n8k16.row.col.f32.bf16.bf16.f32 "
        "{%0,%1,%2,%3}, {%4,%5,%6,%7}, {%8,%9}, {%0,%1,%2,%3};"
        : "+f"(c[0]), "+f"(c[1]), "+f"(c[2]), "+f"(c[3])
        : "r"(a0), "r"(a1), "r"(a2), "r"(a3), "r"(b0), "r"(b1));
}

// ---------------------------------------------------------------------------
__global__ void k_detect(const void* ei, int N) {
    const long long* p = (const long long*)ei;
    bool ok64 = true;
#pragma unroll
    for (int i = 0; i < 8; i++) {
        long long v = p[i];
        if (v < 0 || v >= N) ok64 = false;
    }
    g_is64 = ok64 ? 1 : 0;
}
__device__ __forceinline__ int edge_src(const void* ei, int e) {
    return g_is64 ? (int)__ldg((const long long*)ei + e) : __ldg((const int*)ei + e);
}
__device__ __forceinline__ int edge_dst(const void* ei, int e, int E) {
    return g_is64 ? (int)__ldg((const long long*)ei + (size_t)E + e)
                  : __ldg((const int*)ei + (size_t)E + e);
}

// ---------------------------------------------------------------------------
// CSR build
// ---------------------------------------------------------------------------
__global__ void k_zero(int N) {
    int i = blockIdx.x * blockDim.x + threadIdx.x;
    if (i <= N) g_deg[i] = 0;
}
__global__ void k_hist(const void* __restrict__ ei, int E) {
    int e = blockIdx.x * blockDim.x + threadIdx.x;
    if (e < E) atomicAdd(&g_deg[edge_dst(ei, e, E)], 1);
}
__global__ void __launch_bounds__(1024) k_scan1(int n) {
    __shared__ int warp_sums[32];
    const int tid = threadIdx.x, lane = tid & 31, wid = tid >> 5;
    int i = blockIdx.x * 1024 + tid;
    int v = (i < n) ? g_deg[i] : 0;
    int x = v;
#pragma unroll
    for (int off = 1; off < 32; off <<= 1) {
        int y = __shfl_up_sync(0xFFFFFFFFu, x, off);
        if (lane >= off) x += y;
    }
    if (lane == 31) warp_sums[wid] = x;
    __syncthreads();
    if (wid == 0) {
        int s = warp_sums[lane];
#pragma unroll
        for (int off = 1; off < 32; off <<= 1) {
            int y = __shfl_up_sync(0xFFFFFFFFu, s, off);
            if (lane >= off) s += y;
        }
        warp_sums[lane] = s;
    }
    __syncthreads();
    int incl = x + (wid ? warp_sums[wid - 1] : 0);
    if (i < n) g_off[i] = incl - v;
    if (tid == 1023) g_bsum[blockIdx.x] = incl;
}
__global__ void __launch_bounds__(256) k_scan2(int nb) {
    __shared__ int s[256];
    int tid = threadIdx.x;
    s[tid] = (tid < nb) ? g_bsum[tid] : 0;
    __syncthreads();
#pragma unroll
    for (int off = 1; off < 256; off <<= 1) {
        int v = (tid >= off) ? s[tid - off] : 0;
        __syncthreads();
        s[tid] += v;
        __syncthreads();
    }
    if (tid < nb) g_bpre[tid] = s[tid] - g_bsum[tid];
}
__global__ void __launch_bounds__(1024) k_scan3(int n, int E) {
    int i = blockIdx.x * 1024 + threadIdx.x;
    if (i < n) {
        int v = g_off[i] + g_bpre[blockIdx.x];
        g_off[i] = v;
        g_cur[i] = v;
    }
    if (i == n) g_off[n] = E;
}
__global__ void k_csr(const void* __restrict__ ei, int E) {
    int e = blockIdx.x * blockDim.x + threadIdx.x;
    if (e >= E) return;
    int s = edge_src(ei, e);
    int d = edge_dst(ei, e, E);
    int pos = atomicAdd(&g_cur[d], 1);
    g_csrc[pos] = s;
}

// ---------------------------------------------------------------------------
// W^T bf16 split precompute
// ---------------------------------------------------------------------------
__global__ void k_wt(const float* __restrict__ W) {
    int i = blockIdx.x * blockDim.x + threadIdx.x;
    if (i >= 128 * 128) return;
    int n = i >> 7, k = i & 127;
    float v = __ldg(W + k * 128 + n);
    float hi = bf16r(v);
    g_wtb_hi[i] = __float2bfloat16(v);
    g_wtb_lo[i] = __float2bfloat16(v - hi);
}

// ---------------------------------------------------------------------------
// GEMM via mma.sync m16n8k16 bf16, 3-term split + fused logits.
// Epilogue writes fp16 h (g_hf) + fp32 logits. (unchanged from R9)
// ---------------------------------------------------------------------------
#define AS_STRIDE 136
#define SM_AHI 0
#define SM_ALO (128 * AS_STRIDE * 2)
#define SM_BHI (SM_ALO + 128 * AS_STRIDE * 2)
#define SM_BLO (SM_BHI + 128 * AS_STRIDE * 2)
#define SM_ATT (SM_BLO + 128 * AS_STRIDE * 2)
#define SM_TOT (SM_ATT + 1024)

__global__ void __launch_bounds__(256, 1)
k_gemm_mma(const float* __restrict__ x,
           const float* __restrict__ att_src, const float* __restrict__ att_dst,
           int N) {
    extern __shared__ char smem[];
    const int tid = threadIdx.x;
    const int row0 = blockIdx.x * 128;

    if (tid < 128)       *(float*)(smem + SM_ATT + tid * 4) = att_src[tid];
    else if (tid < 256)  *(float*)(smem + SM_ATT + 512 + (tid - 128) * 4) = att_dst[tid - 128];

    const float4* Xg = (const float4*)x;
#pragma unroll
    for (int i = 0; i < 16; i++) {
        int idx = tid + i * 256;
        int m = idx >> 5, kf4 = idx & 31;
        int gr = row0 + m;
        float4 v = (gr < N) ? Xg[(size_t)gr * 32 + kf4]
                            : make_float4(0.f, 0.f, 0.f, 0.f);
        float hx = bf16r(v.x), hy = bf16r(v.y), hz = bf16r(v.z), hw = bf16r(v.w);
        uint2 hi2 = make_uint2(pack_bf2(hx, hy), pack_bf2(hz, hw));
        uint2 lo2 = make_uint2(pack_bf2(v.x - hx, v.y - hy),
                               pack_bf2(v.z - hz, v.w - hw));
        uint32_t off = (uint32_t)(m * AS_STRIDE + kf4 * 4) * 2;
        *(uint2*)(smem + SM_AHI + off) = hi2;
        *(uint2*)(smem + SM_ALO + off) = lo2;
    }
#pragma unroll
    for (int i = 0; i < 8; i++) {
        int idx = tid + i * 256;
        int n = idx >> 4, kb = (idx & 15) * 8;
        uint32_t off = (uint32_t)(n * AS_STRIDE + kb) * 2;
        *(uint4*)(smem + SM_BHI + off) = *(const uint4*)(g_wtb_hi + n * 128 + kb);
        *(uint4*)(smem + SM_BLO + off) = *(const uint4*)(g_wtb_lo + n * 128 + kb);
    }
    __syncthreads();

    const int w = tid >> 5, lane = tid & 31;
    const int mw = w & 3, nw = w >> 2;
    const int m0 = mw * 32, n0 = nw * 64;
    const int g = lane >> 2, q = lane & 3;

    float acc[2][8][4];
#pragma unroll
    for (int a = 0; a < 2; a++)
#pragma unroll
        for (int b = 0; b < 8; b++)
#pragma unroll
            for (int c = 0; c < 4; c++) acc[a][b][c] = 0.f;

    const char* sA_hi = smem + SM_AHI;
    const char* sA_lo = smem + SM_ALO;
    const char* sB_hi = smem + SM_BHI;
    const char* sB_lo = smem + SM_BLO;

#pragma unroll
    for (int ka = 0; ka < 8; ka++) {
        const int k0 = ka * 16 + q * 2;
        uint32_t ah[2][4], al[2][4];
#pragma unroll
        for (int ma = 0; ma < 2; ma++) {
            int r = m0 + ma * 16 + g;
            uint32_t o00 = (uint32_t)(r * AS_STRIDE + k0) * 2;
            uint32_t o10 = (uint32_t)((r + 8) * AS_STRIDE + k0) * 2;
            ah[ma][0] = *(const uint32_t*)(sA_hi + o00);
            ah[ma][1] = *(const uint32_t*)(sA_hi + o10);
            ah[ma][2] = *(const uint32_t*)(sA_hi + o00 + 16);
            ah[ma][3] = *(const uint32_t*)(sA_hi + o10 + 16);
            al[ma][0] = *(const uint32_t*)(sA_lo + o00);
            al[ma][1] = *(const uint32_t*)(sA_lo + o10);
            al[ma][2] = *(const uint32_t*)(sA_lo + o00 + 16);
            al[ma][3] = *(const uint32_t*)(sA_lo + o10 + 16);
        }
        uint32_t bh[8][2], bl[8][2];
#pragma unroll
        for (int na = 0; na < 8; na++) {
            int n = n0 + na * 8 + g;
            uint32_t o = (uint32_t)(n * AS_STRIDE + k0) * 2;
            bh[na][0] = *(const uint32_t*)(sB_hi + o);
            bh[na][1] = *(const uint32_t*)(sB_hi + o + 16);
            bl[na][0] = *(const uint32_t*)(sB_lo + o);
            bl[na][1] = *(const uint32_t*)(sB_lo + o + 16);
        }
#pragma unroll
        for (int ma = 0; ma < 2; ma++)
#pragma unroll
            for (int na = 0; na < 8; na++) {
                mma_bf16(acc[ma][na], ah[ma][0], ah[ma][1], ah[ma][2], ah[ma][3],
                         bh[na][0], bh[na][1]);
                mma_bf16(acc[ma][na], ah[ma][0], ah[ma][1], ah[ma][2], ah[ma][3],
                         bl[na][0], bl[na][1]);
                mma_bf16(acc[ma][na], al[ma][0], al[ma][1], al[ma][2], al[ma][3],
                         bh[na][0], bh[na][1]);
            }
    }

    const float* s_as = (const float*)(smem + SM_ATT);
    const float* s_ad = (const float*)(smem + SM_ATT + 512);

#pragma unroll
    for (int ma = 0; ma < 2; ma++) {
#pragma unroll
        for (int half = 0; half < 2; half++) {
            int row = row0 + m0 + ma * 16 + g + half * 8;
            float as0 = 0.f, as1 = 0.f, ad0 = 0.f, ad1 = 0.f;
#pragma unroll
            for (int na = 0; na < 8; na++) {
                int col = n0 + na * 8 + q * 2;
                float v0 = acc[ma][na][half * 2];
                float v1 = acc[ma][na][half * 2 + 1];
                if (row < N)
                    *(__half2*)(g_hf + (size_t)row * 128 + col) =
                        __floats2half2_rn(v0, v1);
                float ps = v0 * s_as[col] + v1 * s_as[col + 1];
                float pd = v0 * s_ad[col] + v1 * s_ad[col + 1];
                if (na < 4) { as0 += ps; ad0 += pd; }
                else        { as1 += ps; ad1 += pd; }
            }
#pragma unroll
            for (int off = 1; off < 4; off <<= 1) {
                as0 += __shfl_xor_sync(0xFFFFFFFFu, as0, off);
                as1 += __shfl_xor_sync(0xFFFFFFFFu, as1, off);
                ad0 += __shfl_xor_sync(0xFFFFFFFFu, ad0, off);
                ad1 += __shfl_xor_sync(0xFFFFFFFFu, ad1, off);
            }
            if (q == 0 && row < N) {
                int hb = nw * 2;
                g_asrc[(size_t)row * 4 + hb]     = as0;
                g_asrc[(size_t)row * 4 + hb + 1] = as1;
                g_adst[(size_t)row * 4 + hb]     = ad0;
                g_adst[(size_t)row * 4 + hb + 1] = ad1;
            }
        }
    }
}

// ---------------------------------------------------------------------------
// Aggregation v3: chunked, latency-hiding.
// Phase A (per 32-edge chunk): lane l loads csrc[beg+l] (coalesced) and
// asrc[s_l] (float4) in parallel across lanes, computes all-4-head p,
// stashes (s, p[4]) in smem. Phase B: inner loop does only independent
// fp16 h-row loads (s/p via smem broadcast), unroll 4 -> high MLP.
// ---------------------------------------------------------------------------
__global__ void __launch_bounds__(256) k_agg(float* __restrict__ out,
                                             const float* __restrict__ bias,
                                             int N) {
    __shared__ float p_sm[8][4][32];
    __shared__ int   s_sm[8][32];
    const int wib = threadIdx.x >> 5;
    const int d = (blockIdx.x * blockDim.x + threadIdx.x) >> 5;
    const int lane = threadIdx.x & 31;
    if (d >= N) return;
    const int hh = lane >> 3;

    const float4 ad4 = *(const float4*)(g_adst + (size_t)d * 4);
    const float adst_h = sel4(ad4, hh);
    const int beg = g_off[d];
    const int end = g_off[d + 1];

    // self loop seeds the accumulators
    float den = __expf(lrelu(__ldg(&g_asrc[(size_t)d * 4 + hh]) + adst_h));
    float4 acc;
    {
        uint2 u = __ldg((const uint2*)(g_hf + (size_t)d * 128) + lane);
        float2 f0 = __half22float2(*(__half2*)&u.x);
        float2 f1 = __half22float2(*(__half2*)&u.y);
        acc = make_float4(den * f0.x, den * f0.y, den * f1.x, den * f1.y);
    }

    for (int base = beg; base < end; base += 32) {
        const int cnt = min(32, end - base);
        // Phase A: parallel index + logit loads, all-head p
        {
            int j = base + lane;
            int s = d;
            float4 p4 = make_float4(0.f, 0.f, 0.f, 0.f);
            if (j < end) {
                s = __ldg(&g_csrc[j]);
                float4 a4 = *(const float4*)(g_asrc + (size_t)s * 4);
                p4.x = __expf(lrelu(a4.x + ad4.x));
                p4.y = __expf(lrelu(a4.y + ad4.y));
                p4.z = __expf(lrelu(a4.z + ad4.z));
                p4.w = __expf(lrelu(a4.w + ad4.w));
            }
            s_sm[wib][lane] = s;
            p_sm[wib][0][lane] = p4.x;
            p_sm[wib][1][lane] = p4.y;
            p_sm[wib][2][lane] = p4.z;
            p_sm[wib][3][lane] = p4.w;
        }
        __syncwarp();
        // Phase B: independent h-row gathers
#pragma unroll 4
        for (int t = 0; t < cnt; t++) {
            int ss = s_sm[wib][t];
            float p = p_sm[wib][hh][t];
            den += p;
            uint2 u = __ldg((const uint2*)(g_hf + (size_t)ss * 128) + lane);
            float2 f0 = __half22float2(*(__half2*)&u.x);
            float2 f1 = __half22float2(*(__half2*)&u.y);
            acc.x = fmaf(p, f0.x, acc.x);
            acc.y = fmaf(p, f0.y, acc.y);
            acc.z = fmaf(p, f1.x, acc.z);
            acc.w = fmaf(p, f1.y, acc.w);
        }
        __syncwarp();
    }

    const float inv = __fdividef(1.0f, den);
    float4 b4 = ((const float4*)bias)[lane];
    acc.x = fmaf(acc.x, inv, b4.x);
    acc.y = fmaf(acc.y, inv, b4.y);
    acc.z = fmaf(acc.z, inv, b4.z);
    acc.w = fmaf(acc.w, inv, b4.w);
    ((float4*)(out + (size_t)d * 128))[lane] = acc;
}

// ---------------------------------------------------------------------------
extern "C" void kernel_launch(void* const* d_in, const int* in_sizes, int n_in,
                              void* d_out, int out_size) {
    int idx_W = -1;
    int small[3] = {-1, -1, -1}; int ns = 0;
    for (int i = 0; i < n_in; i++) {
        int sz = in_sizes[i];
        if (sz == 128 && ns < 3)  small[ns++] = i;
        else if (sz == 128 * 128) idx_W = i;
    }
    int idx_x = -1, idx_e = -1;
    for (int i = 0; i < n_in; i++) {
        if (in_sizes[i] == 128 || in_sizes[i] == 128 * 128) continue;
        if (idx_x < 0 || in_sizes[i] > in_sizes[idx_x]) { idx_e = idx_x; idx_x = i; }
        else if (idx_e < 0 || in_sizes[i] > in_sizes[idx_e]) { idx_e = i; }
    }
    int idx_asrc, idx_adst, idx_bias;
    if (idx_x < small[0]) { idx_asrc = small[0]; idx_adst = small[1]; idx_bias = small[2]; }
    else                  { idx_adst = small[0]; idx_asrc = small[1]; idx_bias = small[2]; }

    const float* x       = (const float*)d_in[idx_x];
    const void*  ei      = d_in[idx_e];
    const float* W       = (const float*)d_in[idx_W];
    const float* att_src = (const float*)d_in[idx_asrc];
    const float* att_dst = (const float*)d_in[idx_adst];
    const float* bias    = (const float*)d_in[idx_bias];
    float* out           = (float*)d_out;

    const int N = in_sizes[idx_x] / 128;
    const int E = in_sizes[idx_e] / 2;
    const int nb = (N + 1023) / 1024;

    static cudaStream_t s2 = nullptr;
    static cudaEvent_t evFork = nullptr, evJoin = nullptr;
    if (!s2) {
        cudaFuncSetAttribute(k_gemm_mma, cudaFuncAttributeMaxDynamicSharedMemorySize, SM_TOT);
        cudaStreamCreateWithFlags(&s2, cudaStreamNonBlocking);
        cudaEventCreateWithFlags(&evFork, cudaEventDisableTiming);
        cudaEventCreateWithFlags(&evJoin, cudaEventDisableTiming);
    }

    cudaEventRecord(evFork, 0);
    cudaStreamWaitEvent(s2, evFork, 0);

    // --- s2: CSR build
    k_detect<<<1, 1, 0, s2>>>(ei, N);
    k_zero<<<(N + 256) / 256, 256, 0, s2>>>(N);
    k_hist<<<(E + 255) / 256, 256, 0, s2>>>(ei, E);
    k_scan1<<<nb, 1024, 0, s2>>>(N);
    k_scan2<<<1, 256, 0, s2>>>(nb);
    k_scan3<<<nb + 1, 1024, 0, s2>>>(N, E);
    k_csr<<<(E + 255) / 256, 256, 0, s2>>>(ei, E);

    // --- default stream: GEMM (tensor core) + fused logits
    k_wt<<<(128 * 128 + 255) / 256, 256>>>(W);
    k_gemm_mma<<<(N + 127) / 128, 256, SM_TOT>>>(x, att_src, att_dst, N);

    // Join, then aggregate
    cudaEventRecord(evJoin, s2);
    cudaStreamWaitEvent(0, evJoin, 0);
    {
        long long threads = (long long)N * 32;
        int blocks = (int)((threads + 255) / 256);
        k_agg<<<blocks, 256>>>(out, bias, N);
    }
}